// round 1
// baseline (speedup 1.0000x reference)
#include <cuda_runtime.h>
#include <math.h>
#include <stdint.h>

// Shapes (fixed for this problem)
#define BB     16
#define LSEQ   1024
#define DDIM   768
#define HDIM   256
#define NHEAD  4
#define OUTD   768
#define BLROWS (BB*LSEQ)          // 16384
#define PPAD   260                // padded smem row stride (floats) for 256-wide tiles

// ---------------- scratch (device globals; no allocation) ----------------
__device__ float g_h[(size_t)NHEAD * BLROWS * HDIM];     // 64 MB
__device__ float g_t[(size_t)NHEAD * BLROWS * HDIM];     // 64 MB
__device__ float g_esrc[NHEAD * BLROWS];
__device__ float g_edst[NHEAD * BLROWS];
__device__ float g_partial[NHEAD * BB * 32 * HDIM];      // per-CTA row-sums

// ---------------- helpers ----------------
__device__ __forceinline__ float wredsum(float v) {
    #pragma unroll
    for (int o = 16; o; o >>= 1) v += __shfl_xor_sync(0xffffffffu, v, o);
    return v;
}
__device__ __forceinline__ float sigf(float x) {
    // matches jax.nn.sigmoid's stable form in fp32
    if (x >= 0.f) { float z = expf(-x); return 1.f / (1.f + z); }
    float z = expf(x); return z / (1.f + z);
}

// ---------------- generic tiled GEMM: C[M,N] = A[M,K] @ B[K,N] (+bias) ----
// grid: (N/64, M/64, batch); block: 256
__global__ void __launch_bounds__(256) gemm64(
    const float* __restrict__ A, const float* __restrict__ Bm,
    const float* __restrict__ bias, float* __restrict__ C,
    int M, int N, int K,
    long aStride, long bStride, long biasStride, long cStride)
{
    int z = blockIdx.z;
    A += (long)z * aStride;
    Bm += (long)z * bStride;
    C += (long)z * cStride;
    if (bias) bias += (long)z * biasStride;

    __shared__ float As[16][64];
    __shared__ float Bs[16][64];

    int m0 = blockIdx.y * 64, n0 = blockIdx.x * 64;
    int tid = threadIdx.x;
    int tx = tid & 15, ty = tid >> 4;

    float acc[4][4];
    #pragma unroll
    for (int i = 0; i < 4; ++i)
        #pragma unroll
        for (int j = 0; j < 4; ++j) acc[i][j] = 0.f;

    for (int k0 = 0; k0 < K; k0 += 16) {
        {   // load A tile 64x16, store transposed
            int idx = tid * 4;
            int row = idx >> 4;
            int kk  = idx & 15;
            float4 v = *(const float4*)&A[(long)(m0 + row) * K + k0 + kk];
            As[kk + 0][row] = v.x; As[kk + 1][row] = v.y;
            As[kk + 2][row] = v.z; As[kk + 3][row] = v.w;
        }
        {   // load B tile 16x64
            int idx = tid * 4;
            int kr = idx >> 6;
            int nn = idx & 63;
            *(float4*)&Bs[kr][nn] = *(const float4*)&Bm[(long)(k0 + kr) * N + n0 + nn];
        }
        __syncthreads();
        #pragma unroll
        for (int k = 0; k < 16; ++k) {
            float4 a = *(const float4*)&As[k][ty * 4];
            float4 b = *(const float4*)&Bs[k][tx * 4];
            acc[0][0] = fmaf(a.x, b.x, acc[0][0]); acc[0][1] = fmaf(a.x, b.y, acc[0][1]);
            acc[0][2] = fmaf(a.x, b.z, acc[0][2]); acc[0][3] = fmaf(a.x, b.w, acc[0][3]);
            acc[1][0] = fmaf(a.y, b.x, acc[1][0]); acc[1][1] = fmaf(a.y, b.y, acc[1][1]);
            acc[1][2] = fmaf(a.y, b.z, acc[1][2]); acc[1][3] = fmaf(a.y, b.w, acc[1][3]);
            acc[2][0] = fmaf(a.z, b.x, acc[2][0]); acc[2][1] = fmaf(a.z, b.y, acc[2][1]);
            acc[2][2] = fmaf(a.z, b.z, acc[2][2]); acc[2][3] = fmaf(a.z, b.w, acc[2][3]);
            acc[3][0] = fmaf(a.w, b.x, acc[3][0]); acc[3][1] = fmaf(a.w, b.y, acc[3][1]);
            acc[3][2] = fmaf(a.w, b.z, acc[3][2]); acc[3][3] = fmaf(a.w, b.w, acc[3][3]);
        }
        __syncthreads();
    }
    #pragma unroll
    for (int i = 0; i < 4; ++i) {
        float4 o;
        o.x = acc[i][0]; o.y = acc[i][1]; o.z = acc[i][2]; o.w = acc[i][3];
        if (bias) {
            const float* bp = &bias[n0 + tx * 4];
            o.x += bp[0]; o.y += bp[1]; o.z += bp[2]; o.w += bp[3];
        }
        *(float4*)&C[(long)(m0 + ty * 4 + i) * N + n0 + tx * 4] = o;
    }
}

// ---------------- fused LayerNorm (in-place on g_h) + e_src/e_dst dots ----
// one warp per row of 256; 8 warps per CTA; rows = NHEAD*BLROWS
__global__ void __launch_bounds__(256) ln_att_kernel(
    const float* __restrict__ lng, const float* __restrict__ lnb,
    const float* __restrict__ Watt)
{
    int row  = blockIdx.x * 8 + (threadIdx.x >> 5);
    int lane = threadIdx.x & 31;
    int n = row >> 14;                     // / BLROWS
    float* hr = g_h + (long)row * HDIM;

    float v[8];
    #pragma unroll
    for (int q = 0; q < 8; ++q) v[q] = hr[q * 32 + lane];

    float s = 0.f;
    #pragma unroll
    for (int q = 0; q < 8; ++q) s += v[q];
    s = wredsum(s);
    float mu = s * (1.f / 256.f);

    float s2 = 0.f;
    #pragma unroll
    for (int q = 0; q < 8; ++q) { float d = v[q] - mu; s2 += d * d; }
    s2 = wredsum(s2);
    float rstd = rsqrtf(s2 * (1.f / 256.f) + 1e-5f);

    const float* g  = lng + n * HDIM;
    const float* bb = lnb + n * HDIM;
    const float* ws = Watt + n * 2 * HDIM;
    const float* wd = ws + HDIM;

    float a1 = 0.f, a2 = 0.f;
    #pragma unroll
    for (int q = 0; q < 8; ++q) {
        int c = q * 32 + lane;
        float o = (v[q] - mu) * rstd * g[c] + bb[c];
        hr[c] = o;
        a1 = fmaf(o, ws[c], a1);
        a2 = fmaf(o, wd[c], a2);
    }
    a1 = wredsum(a1);
    a2 = wredsum(a2);
    if (lane == 0) { g_esrc[row] = a1; g_edst[row] = a2; }
}

// ---------------- fused attention ----------------
// grid: (32 i-blocks, B=16, NH=4); block 256; dyn smem ~205KB
__global__ void __launch_bounds__(256) attn_kernel(const float* __restrict__ batt)
{
    extern __shared__ float sm[];
    float* sA    = sm;                       // 32*1024
    float* sT    = sA + 32 * 1024;           // 32*PPAD (reused as reduce buf later)
    float* sH    = sT + 32 * PPAD;           // 32*PPAD
    float* sE    = sH + 32 * PPAD;           // 1024
    float* sEs   = sE + 1024;                // 32
    int*   sHist = (int*)(sEs + 32);         // 8*256
    int*   sFlag = sHist + 8 * 256;          // 32

    int ib = blockIdx.x, b = blockIdx.y, n = blockIdx.z;
    int tid = threadIdx.x;
    int lane = tid & 31, w = tid >> 5;
    long nb = (long)(n * 16 + b);
    const float* hb = g_h + nb * LSEQ * HDIM;
    const float* tb = g_t + nb * LSEQ * HDIM + (long)ib * 32 * HDIM;
    int erow = n * BLROWS + b * LSEQ;
    int i0 = ib * 32;

    if (tid < 32) sFlag[tid] = 0;
    // load T block (32x256 -> padded)
    {
        const float4* src = (const float4*)tb;
        for (int v = tid; v < 2048; v += 256) {
            int r = v >> 6, c = v & 63;
            ((float4*)(sT + r * PPAD))[c] = src[v];
        }
    }
    for (int j = tid; j < 1024; j += 256) sE[j] = g_edst[erow + j];
    if (tid < 32) sEs[tid] = g_esrc[erow + i0 + tid];

    int tx = tid & 15, ty = tid >> 4;
    int r0 = ty * 2, r1 = r0 + 1;
    int c0 = tx, c1 = tx + 16;

    // ---- Phase A: S = T @ H^T, A = sigmoid(S) into sA ----
    for (int jt = 0; jt < 32; ++jt) {
        __syncthreads();
        {
            const float4* src = (const float4*)(hb + (long)jt * 32 * HDIM);
            for (int v = tid; v < 2048; v += 256) {
                int r = v >> 6, c = v & 63;
                ((float4*)(sH + r * PPAD))[c] = src[v];
            }
        }
        __syncthreads();
        const float4* T4 = (const float4*)sT;
        const float4* H4 = (const float4*)sH;
        float a00 = 0.f, a01 = 0.f, a10 = 0.f, a11 = 0.f;
        #pragma unroll 8
        for (int k4 = 0; k4 < 64; ++k4) {
            float4 ta0 = T4[r0 * (PPAD / 4) + k4];
            float4 ta1 = T4[r1 * (PPAD / 4) + k4];
            float4 hb0 = H4[c0 * (PPAD / 4) + k4];
            float4 hb1 = H4[c1 * (PPAD / 4) + k4];
            a00 = fmaf(ta0.x, hb0.x, a00); a00 = fmaf(ta0.y, hb0.y, a00);
            a00 = fmaf(ta0.z, hb0.z, a00); a00 = fmaf(ta0.w, hb0.w, a00);
            a01 = fmaf(ta0.x, hb1.x, a01); a01 = fmaf(ta0.y, hb1.y, a01);
            a01 = fmaf(ta0.z, hb1.z, a01); a01 = fmaf(ta0.w, hb1.w, a01);
            a10 = fmaf(ta1.x, hb0.x, a10); a10 = fmaf(ta1.y, hb0.y, a10);
            a10 = fmaf(ta1.z, hb0.z, a10); a10 = fmaf(ta1.w, hb0.w, a10);
            a11 = fmaf(ta1.x, hb1.x, a11); a11 = fmaf(ta1.y, hb1.y, a11);
            a11 = fmaf(ta1.z, hb1.z, a11); a11 = fmaf(ta1.w, hb1.w, a11);
        }
        sA[r0 * 1024 + jt * 32 + c0] = sigf(a00);
        sA[r0 * 1024 + jt * 32 + c1] = sigf(a01);
        sA[r1 * 1024 + jt * 32 + c0] = sigf(a10);
        sA[r1 * 1024 + jt * 32 + c1] = sigf(a11);
    }
    __syncthreads();

    // ---- Phase B+C: per-row exact quantile (radix select) + masked softmax ----
    float battn = batt[n];
    const float frac = (float)(0.7 * 1023.0 - 716.0);   // ~0.1
    int* hist = sHist + w * 256;
    for (int rr = 0; rr < 4; ++rr) {
        int r = w * 4 + rr;
        const float* Ar = sA + r * 1024;

        unsigned prefix = 0; int rank = 716;
        for (int p = 3; p >= 0; --p) {
            for (int q2 = lane; q2 < 256; q2 += 32) hist[q2] = 0;
            __syncwarp();
            unsigned himask = (p == 3) ? 0u : (0xFFFFFFFFu << ((p + 1) * 8));
            for (int j = lane; j < 1024; j += 32) {
                unsigned key = __float_as_uint(Ar[j]);
                if ((key & himask) == prefix)
                    atomicAdd(&hist[(key >> (p * 8)) & 0xFF], 1);
            }
            __syncwarp();
            int part = 0;
            #pragma unroll
            for (int q2 = 0; q2 < 8; ++q2) part += hist[lane * 8 + q2];
            int scan = part;
            #pragma unroll
            for (int o = 1; o < 32; o <<= 1) {
                int vv = __shfl_up_sync(0xffffffffu, scan, o);
                if (lane >= o) scan += vv;
            }
            int excl = scan - part;
            unsigned vote = __ballot_sync(0xffffffffu, (excl <= rank) && (rank < excl + part));
            int srcl = __ffs(vote) - 1;
            int binsel = 0, nrank = 0;
            if (lane == srcl) {
                int cum = excl;
                #pragma unroll
                for (int q2 = 0; q2 < 8; ++q2) {
                    int c = hist[lane * 8 + q2];
                    if (cum + c > rank) { binsel = lane * 8 + q2; nrank = rank - cum; break; }
                    cum += c;
                }
            }
            binsel = __shfl_sync(0xffffffffu, binsel, srcl);
            rank   = __shfl_sync(0xffffffffu, nrank, srcl);
            prefix |= (unsigned)binsel << (p * 8);
            __syncwarp();
        }
        float v1 = __uint_as_float(prefix);
        int cnt = 0; unsigned mn = 0xFFFFFFFFu;
        for (int j = lane; j < 1024; j += 32) {
            unsigned key = __float_as_uint(Ar[j]);
            if (key <= prefix) cnt++; else mn = min(mn, key);
        }
        #pragma unroll
        for (int o = 16; o; o >>= 1) {
            cnt += __shfl_xor_sync(0xffffffffu, cnt, o);
            mn = min(mn, __shfl_xor_sync(0xffffffffu, mn, o));
        }
        float v2 = (cnt >= 718) ? v1 : __uint_as_float(mn);
        float delta = v1 + frac * (v2 - v1);

        // masked softmax of e, write alpha back into sA row
        int ig = i0 + r;
        float es = sEs[r];
        float m = -1e30f;
        for (int j = lane; j < 1024; j += 32) {
            if (Ar[j] > delta || j == ig) {
                float x = es + sE[j] + battn;
                float e = x > 0.f ? x : 0.01f * x;
                m = fmaxf(m, e);
            }
        }
        #pragma unroll
        for (int o = 16; o; o >>= 1) m = fmaxf(m, __shfl_xor_sync(0xffffffffu, m, o));
        float ssum = 0.f;
        for (int j = lane; j < 1024; j += 32) {
            if (Ar[j] > delta || j == ig) {
                float x = es + sE[j] + battn;
                float e = x > 0.f ? x : 0.01f * x;
                ssum += expf(e - m);
            }
        }
        ssum = wredsum(ssum);
        float inv = 1.f / ssum;
        for (int j = lane; j < 1024; j += 32) {
            bool msk = (Ar[j] > delta) || (j == ig);
            float aj = 0.f;
            if (msk) {
                float x = es + sE[j] + battn;
                float e = x > 0.f ? x : 0.01f * x;
                aj = expf(e - m) * inv;
            }
            sA[r * 1024 + j] = aj;
            if (aj != 0.f) sFlag[j >> 5] = 1;
        }
        __syncwarp();
    }
    __syncthreads();

    // ---- Phase D: out = alpha @ H, skipping all-zero alpha tiles ----
    float acc0[16], acc1[16];
    #pragma unroll
    for (int q = 0; q < 16; ++q) { acc0[q] = 0.f; acc1[q] = 0.f; }
    for (int jt = 0; jt < 32; ++jt) {
        if (sFlag[jt] == 0) continue;            // uniform across CTA
        __syncthreads();
        {
            const float4* src = (const float4*)(hb + (long)jt * 32 * HDIM);
            for (int v = tid; v < 2048; v += 256) {
                int r = v >> 6, c = v & 63;
                ((float4*)(sH + r * PPAD))[c] = src[v];
            }
        }
        __syncthreads();
        #pragma unroll 2
        for (int k = 0; k < 32; ++k) {
            float a0 = sA[r0 * 1024 + jt * 32 + k];
            float a1 = sA[r1 * 1024 + jt * 32 + k];
            const float* hr2 = sH + k * PPAD + tx * 4;
            #pragma unroll
            for (int cc = 0; cc < 4; ++cc) {
                float4 hv = *(const float4*)(hr2 + cc * 64);
                acc0[cc * 4 + 0] = fmaf(a0, hv.x, acc0[cc * 4 + 0]);
                acc0[cc * 4 + 1] = fmaf(a0, hv.y, acc0[cc * 4 + 1]);
                acc0[cc * 4 + 2] = fmaf(a0, hv.z, acc0[cc * 4 + 2]);
                acc0[cc * 4 + 3] = fmaf(a0, hv.w, acc0[cc * 4 + 3]);
                acc1[cc * 4 + 0] = fmaf(a1, hv.x, acc1[cc * 4 + 0]);
                acc1[cc * 4 + 1] = fmaf(a1, hv.y, acc1[cc * 4 + 1]);
                acc1[cc * 4 + 2] = fmaf(a1, hv.z, acc1[cc * 4 + 2]);
                acc1[cc * 4 + 3] = fmaf(a1, hv.w, acc1[cc * 4 + 3]);
            }
        }
    }
    __syncthreads();
    // reduce 32 rows -> per-column partial sums (reuse sT as 16x256 buffer)
    float* red = sT;
    #pragma unroll
    for (int cc = 0; cc < 4; ++cc)
        #pragma unroll
        for (int q = 0; q < 4; ++q) {
            int col = tx * 4 + cc * 64 + q;
            red[ty * 256 + col] = acc0[cc * 4 + q] + acc1[cc * 4 + q];
        }
    __syncthreads();
    {
        int col = tid;
        float s = 0.f;
        #pragma unroll
        for (int yy = 0; yy < 16; ++yy) s += red[yy * 256 + col];
        g_partial[((nb) * 32 + ib) * 256 + col] = s;
    }
}

// ---------------- final: means -> 3 GEMMs -> LN -> d_out ----------------
// grid (3, 16); block 256
__global__ void __launch_bounds__(256) final_kernel(
    const float* __restrict__ W0, const float* __restrict__ b0,
    const float* __restrict__ W1, const float* __restrict__ b1,
    const float* __restrict__ W2, const float* __restrict__ b2,
    const float* __restrict__ g0, const float* __restrict__ be0,
    const float* __restrict__ g1, const float* __restrict__ be1,
    const float* __restrict__ g2, const float* __restrict__ be2,
    float* __restrict__ out)
{
    __shared__ float vin[1024];
    __shared__ float red[40];
    int which = blockIdx.x, b = blockIdx.y, tid = threadIdx.x;
    int K = (which == 2) ? 1024 : 512;
    int hb2 = (which == 1) ? 2 : 0;

    for (int e = tid; e < K; e += 256) {
        int n = hb2 + (e >> 8), col = e & 255;
        const float* p = g_partial + ((long)(n * 16 + b) * 32) * 256 + col;
        float s = 0.f;
        #pragma unroll
        for (int ibk = 0; ibk < 32; ++ibk) s += p[ibk * 256];
        vin[e] = s * (1.f / 1024.f);
    }
    __syncthreads();

    const float* W  = (which == 0) ? W0 : ((which == 1) ? W1 : W2);
    const float* bi = (which == 0) ? b0 : ((which == 1) ? b1 : b2);
    const float* g  = (which == 0) ? g0 : ((which == 1) ? g1 : g2);
    const float* be = (which == 0) ? be0 : ((which == 1) ? be1 : be2);

    float acc3[3];
    #pragma unroll
    for (int oi = 0; oi < 3; ++oi) {
        int o = tid + oi * 256;
        float a = bi[o];
        for (int k = 0; k < K; ++k) a = fmaf(vin[k], W[(long)k * OUTD + o], a);
        acc3[oi] = a;
    }

    // LN over 768
    float ls = acc3[0] + acc3[1] + acc3[2];
    ls = wredsum(ls);
    if ((tid & 31) == 0) red[tid >> 5] = ls;
    __syncthreads();
    if (tid == 0) {
        float s = 0.f;
        for (int q = 0; q < 8; ++q) s += red[q];
        red[32] = s * (1.f / 768.f);
    }
    __syncthreads();
    float mu = red[32];
    __syncthreads();
    float vv = 0.f;
    #pragma unroll
    for (int oi = 0; oi < 3; ++oi) { float d = acc3[oi] - mu; vv += d * d; }
    vv = wredsum(vv);
    if ((tid & 31) == 0) red[tid >> 5] = vv;
    __syncthreads();
    if (tid == 0) {
        float s = 0.f;
        for (int q = 0; q < 8; ++q) s += red[q];
        red[33] = s * (1.f / 768.f);
    }
    __syncthreads();
    float rstd = rsqrtf(red[33] + 1e-5f);
    #pragma unroll
    for (int oi = 0; oi < 3; ++oi) {
        int o = tid + oi * 256;
        out[(long)which * BB * OUTD + (long)b * OUTD + o] = (acc3[oi] - mu) * rstd * g[o] + be[o];
    }
}

// ---------------- launch ----------------
extern "C" void kernel_launch(void* const* d_in, const int* in_sizes, int n_in,
                              void* d_out, int out_size)
{
    const float* x    = (const float*)d_in[0];
    const float* Wfc  = (const float*)d_in[1];
    const float* bfc  = (const float*)d_in[2];
    const float* lng  = (const float*)d_in[3];
    const float* lnb  = (const float*)d_in[4];
    const float* adjw = (const float*)d_in[5];
    const float* Watt = (const float*)d_in[6];
    const float* batt = (const float*)d_in[7];
    const float* Wl = (const float*)d_in[8];  const float* bl = (const float*)d_in[9];
    const float* Ws = (const float*)d_in[10]; const float* bs = (const float*)d_in[11];
    const float* Wc = (const float*)d_in[12]; const float* bc = (const float*)d_in[13];
    const float* gl = (const float*)d_in[14]; const float* bel = (const float*)d_in[15];
    const float* gs = (const float*)d_in[16]; const float* bes = (const float*)d_in[17];
    const float* gc = (const float*)d_in[18]; const float* bec = (const float*)d_in[19];
    float* out = (float*)d_out;

    float *hp = nullptr, *tp = nullptr;
    cudaGetSymbolAddress((void**)&hp, g_h);
    cudaGetSymbolAddress((void**)&tp, g_t);

    // 1) h_pre = x @ Wfc + bfc  (per head)
    gemm64<<<dim3(HDIM / 64, BLROWS / 64, NHEAD), 256>>>(
        x, Wfc, bfc, hp,
        BLROWS, HDIM, DDIM,
        0L, (long)DDIM * HDIM, (long)HDIM, (long)BLROWS * HDIM);

    // 2) LN in place + e_src/e_dst
    ln_att_kernel<<<(NHEAD * BLROWS) / 8, 256>>>(lng, lnb, Watt);

    // 3) t = h @ adjw  (per head)
    gemm64<<<dim3(HDIM / 64, BLROWS / 64, NHEAD), 256>>>(
        hp, adjw, nullptr, tp,
        BLROWS, HDIM, HDIM,
        (long)BLROWS * HDIM, (long)HDIM * HDIM, 0L, (long)BLROWS * HDIM);

    // 4) fused attention
    const int smemBytes = (32 * 1024 + 2 * 32 * PPAD + 1024 + 32) * 4 + (8 * 256 + 32) * 4;
    cudaFuncSetAttribute(attn_kernel, cudaFuncAttributeMaxDynamicSharedMemorySize, smemBytes);
    attn_kernel<<<dim3(32, BB, NHEAD), 256, smemBytes>>>(batt);

    // 5) finals
    final_kernel<<<dim3(3, BB), 256>>>(Wl, bl, Ws, bs, Wc, bc, gl, bel, gs, bes, gc, bec, out);
}

// round 2
// speedup vs baseline: 1.4866x; 1.4866x over previous
#include <cuda_runtime.h>
#include <math.h>
#include <stdint.h>

// Shapes (fixed for this problem)
#define BB     16
#define LSEQ   1024
#define DDIM   768
#define HDIM   256
#define NHEAD  4
#define OUTD   768
#define BLROWS (BB*LSEQ)          // 16384
#define PPAD   260                // padded smem row stride for Phase D H tiles
#define SHT_STRIDE 520

// ---------------- scratch (device globals; no allocation) ----------------
__device__ float g_h[(size_t)NHEAD * BLROWS * HDIM];     // 64 MB
__device__ float g_t[(size_t)NHEAD * BLROWS * HDIM];     // 64 MB
__device__ float g_esrc[NHEAD * BLROWS];
__device__ float g_edst[NHEAD * BLROWS];
__device__ float g_partial[NHEAD * BB * 32 * HDIM];      // per-CTA row-sums

// ---------------- helpers ----------------
__device__ __forceinline__ float wredsum(float v) {
    #pragma unroll
    for (int o = 16; o; o >>= 1) v += __shfl_xor_sync(0xffffffffu, v, o);
    return v;
}
__device__ __forceinline__ float sigf(float x) {
    if (x >= 0.f) { float z = expf(-x); return 1.f / (1.f + z); }
    float z = expf(x); return z / (1.f + z);
}

// ---------------- SGEMM 128x128, 8x8 microtiles ----------------
// C[M,N] = A[M,K] @ B[K,N] (+bias); grid (N/128, M/128, z); block 256
__global__ void __launch_bounds__(256, 2) gemm128(
    const float* __restrict__ A, const float* __restrict__ Bm,
    const float* __restrict__ bias, float* __restrict__ C,
    int M, int N, int K,
    long aStride, long bStride, long biasStride, long cStride)
{
    int z = blockIdx.z;
    A += (long)z * aStride;
    Bm += (long)z * bStride;
    C += (long)z * cStride;
    if (bias) bias += (long)z * biasStride;

    __shared__ float Ast[16 * 128];   // k-major
    __shared__ float Bs[16 * 128];    // k-major

    int m0 = blockIdx.y * 128, n0 = blockIdx.x * 128;
    int tid = threadIdx.x;
    int rowg = (tid & 3) + ((tid >> 6) << 2);   // 0..15
    int colg = (tid >> 2) & 15;                 // 0..15

    float acc[8][8];
    #pragma unroll
    for (int i = 0; i < 8; ++i)
        #pragma unroll
        for (int j = 0; j < 8; ++j) acc[i][j] = 0.f;

    for (int k0 = 0; k0 < K; k0 += 16) {
        __syncthreads();
        // A tile 128 rows x 16 k, store transposed (k-major)
        #pragma unroll
        for (int q = 0; q < 2; ++q) {
            int idx = tid + q * 256;
            int row = idx >> 2, k4 = idx & 3;
            float4 v = *(const float4*)&A[(long)(m0 + row) * K + k0 + k4 * 4];
            int k = k4 * 4;
            Ast[(k + 0) * 128 + row] = v.x;
            Ast[(k + 1) * 128 + row] = v.y;
            Ast[(k + 2) * 128 + row] = v.z;
            Ast[(k + 3) * 128 + row] = v.w;
        }
        // B tile 16 k x 128 cols, direct copy
        #pragma unroll
        for (int q = 0; q < 2; ++q) {
            int idx = tid + q * 256;
            int kr = idx >> 5, n4 = idx & 31;
            *(float4*)&Bs[kr * 128 + n4 * 4] =
                *(const float4*)&Bm[(long)(k0 + kr) * N + n0 + n4 * 4];
        }
        __syncthreads();
        #pragma unroll
        for (int k = 0; k < 16; ++k) {
            float ar[8], bc[8];
            *(float4*)&ar[0] = *(const float4*)&Ast[k * 128 + rowg * 8];
            *(float4*)&ar[4] = *(const float4*)&Ast[k * 128 + rowg * 8 + 4];
            *(float4*)&bc[0] = *(const float4*)&Bs[k * 128 + colg * 8];
            *(float4*)&bc[4] = *(const float4*)&Bs[k * 128 + colg * 8 + 4];
            #pragma unroll
            for (int i = 0; i < 8; ++i)
                #pragma unroll
                for (int j = 0; j < 8; ++j)
                    acc[i][j] = fmaf(ar[i], bc[j], acc[i][j]);
        }
    }
    #pragma unroll
    for (int i = 0; i < 8; ++i) {
        int r = m0 + rowg * 8 + i;
        #pragma unroll
        for (int jj = 0; jj < 2; ++jj) {
            int c = n0 + colg * 8 + jj * 4;
            float4 o;
            o.x = acc[i][jj * 4 + 0]; o.y = acc[i][jj * 4 + 1];
            o.z = acc[i][jj * 4 + 2]; o.w = acc[i][jj * 4 + 3];
            if (bias) {
                const float* bp = &bias[c];
                o.x += bp[0]; o.y += bp[1]; o.z += bp[2]; o.w += bp[3];
            }
            *(float4*)&C[(long)r * N + c] = o;
        }
    }
}

// ---------------- fused LayerNorm (in-place on g_h) + e_src/e_dst dots ----
__global__ void __launch_bounds__(256) ln_att_kernel(
    const float* __restrict__ lng, const float* __restrict__ lnb,
    const float* __restrict__ Watt)
{
    int row  = blockIdx.x * 8 + (threadIdx.x >> 5);
    int lane = threadIdx.x & 31;
    int n = row >> 14;
    float* hr = g_h + (long)row * HDIM;

    float v[8];
    #pragma unroll
    for (int q = 0; q < 8; ++q) v[q] = hr[q * 32 + lane];

    float s = 0.f;
    #pragma unroll
    for (int q = 0; q < 8; ++q) s += v[q];
    s = wredsum(s);
    float mu = s * (1.f / 256.f);

    float s2 = 0.f;
    #pragma unroll
    for (int q = 0; q < 8; ++q) { float d = v[q] - mu; s2 += d * d; }
    s2 = wredsum(s2);
    float rstd = rsqrtf(s2 * (1.f / 256.f) + 1e-5f);

    const float* g  = lng + n * HDIM;
    const float* bb = lnb + n * HDIM;
    const float* ws = Watt + n * 2 * HDIM;
    const float* wd = ws + HDIM;

    float a1 = 0.f, a2 = 0.f;
    #pragma unroll
    for (int q = 0; q < 8; ++q) {
        int c = q * 32 + lane;
        float o = (v[q] - mu) * rstd * g[c] + bb[c];
        hr[c] = o;
        a1 = fmaf(o, ws[c], a1);
        a2 = fmaf(o, wd[c], a2);
    }
    a1 = wredsum(a1);
    a2 = wredsum(a2);
    if (lane == 0) { g_esrc[row] = a1; g_edst[row] = a2; }
}

// ---------------- fused attention ----------------
// grid: (32 i-blocks, B=16, NH=4); block 256; dyn smem ~205KB
__global__ void __launch_bounds__(256, 1) attn_kernel(const float* __restrict__ batt)
{
    extern __shared__ float sm[];
    float* sA    = sm;                    // 32*1024            [0 .. 32768)
    float* sTt   = sm + 32768;            // 256 k x 32 rows    [32768 .. 40960)
    float* sHt   = sm + 40960;            // 16 k x 520         [40960 .. 49280)
    float* sH    = sm + 32768;            // Phase D reuse: 32 x PPAD (8320 floats)
    float* sE    = sm + 49280;            // 1024
    float* sEs   = sm + 50304;            // 32
    int*   sHist = (int*)(sm + 50336);    // 8*256
    int*   sFlag = (int*)(sm + 52384);    // 32

    int ib = blockIdx.x, b = blockIdx.y, n = blockIdx.z;
    int tid = threadIdx.x;
    int lane = tid & 31, w = tid >> 5;
    long nb = (long)(n * 16 + b);
    const float* hb = g_h + nb * LSEQ * HDIM;
    const float* tb = g_t + nb * LSEQ * HDIM + (long)ib * 32 * HDIM;
    int erow = n * BLROWS + b * LSEQ;
    int i0 = ib * 32;

    if (tid < 32) sFlag[tid] = 0;

    // load T block transposed (k-major: sTt[k][r])
    {
        const float4* tb4 = (const float4*)tb;
        for (int idx = tid; idx < 2048; idx += 256) {
            int r = idx >> 6, k4 = idx & 63;
            float4 v = tb4[r * 64 + k4];
            int k = k4 * 4;
            sTt[(k + 0) * 32 + r] = v.x;
            sTt[(k + 1) * 32 + r] = v.y;
            sTt[(k + 2) * 32 + r] = v.z;
            sTt[(k + 3) * 32 + r] = v.w;
        }
    }
    for (int j = tid; j < 1024; j += 256) sE[j] = g_edst[erow + j];
    if (tid < 32) sEs[tid] = g_esrc[erow + i0 + tid];

    // ---- Phase A: S = T @ H^T, A = sigmoid(S), 8x8 microtiles ----
    {
        int rowg = tid & 3;          // 0..3  (rows 32/8)
        int colg = tid >> 2;         // 0..63 (cols 512/8 per half)
        const float4* hb4 = (const float4*)hb;

        for (int ch = 0; ch < 2; ++ch) {
            float acc[8][8];
            #pragma unroll
            for (int i = 0; i < 8; ++i)
                #pragma unroll
                for (int j = 0; j < 8; ++j) acc[i][j] = 0.f;

            for (int kc = 0; kc < 16; ++kc) {
                __syncthreads();
                // load H chunk: j in [ch*512,+512), k in [kc*16,+16), store k-major
                #pragma unroll
                for (int q = 0; q < 8; ++q) {
                    int idx = tid + q * 256;
                    int j = idx >> 2, k4 = idx & 3;
                    float4 v = hb4[(ch * 512 + j) * 64 + kc * 4 + k4];
                    int k = k4 * 4;
                    sHt[(k + 0) * SHT_STRIDE + j] = v.x;
                    sHt[(k + 1) * SHT_STRIDE + j] = v.y;
                    sHt[(k + 2) * SHT_STRIDE + j] = v.z;
                    sHt[(k + 3) * SHT_STRIDE + j] = v.w;
                }
                __syncthreads();
                #pragma unroll
                for (int k = 0; k < 16; ++k) {
                    float tr[8], hc[8];
                    *(float4*)&tr[0] = *(const float4*)&sTt[(kc * 16 + k) * 32 + rowg * 8];
                    *(float4*)&tr[4] = *(const float4*)&sTt[(kc * 16 + k) * 32 + rowg * 8 + 4];
                    *(float4*)&hc[0] = *(const float4*)&sHt[k * SHT_STRIDE + colg * 8];
                    *(float4*)&hc[4] = *(const float4*)&sHt[k * SHT_STRIDE + colg * 8 + 4];
                    #pragma unroll
                    for (int i = 0; i < 8; ++i)
                        #pragma unroll
                        for (int j = 0; j < 8; ++j)
                            acc[i][j] = fmaf(tr[i], hc[j], acc[i][j]);
                }
            }
            #pragma unroll
            for (int i = 0; i < 8; ++i) {
                int r = rowg * 8 + i;
                #pragma unroll
                for (int j = 0; j < 8; ++j)
                    sA[r * 1024 + ch * 512 + colg * 8 + j] = sigf(acc[i][j]);
            }
        }
    }
    __syncthreads();

    // ---- Phase B+C: per-row quantile + masked softmax (fast path: delta==1) ----
    float battn = batt[n];
    const float frac = (float)(0.7 * 1023.0 - 716.0);   // ~0.1
    int* hist = sHist + w * 256;
    for (int rr = 0; rr < 4; ++rr) {
        int r = w * 4 + rr;
        float* Ar = sA + r * 1024;
        int ig = i0 + r;

        // fast path: if >=308 entries saturate at 1.0f, delta==1.0 exactly and
        // mask = (A > 1.0) | diag = diag only (sigmoid <= 1). alpha is one-hot.
        int cnt1 = 0;
        for (int j = lane; j < 1024; j += 32) cnt1 += (Ar[j] >= 1.0f);
        #pragma unroll
        for (int o = 16; o; o >>= 1) cnt1 += __shfl_xor_sync(0xffffffffu, cnt1, o);

        if (cnt1 >= 308) {
            for (int j = lane; j < 1024; j += 32) Ar[j] = 0.f;
            __syncwarp();
            if (lane == 0) { Ar[ig] = 1.f; sFlag[ig >> 5] = 1; }
            __syncwarp();
            continue;
        }

        // general path: exact radix select for rank 716 (+ rank 717)
        unsigned prefix = 0; int rank = 716;
        for (int p = 3; p >= 0; --p) {
            for (int q2 = lane; q2 < 256; q2 += 32) hist[q2] = 0;
            __syncwarp();
            unsigned himask = (p == 3) ? 0u : (0xFFFFFFFFu << ((p + 1) * 8));
            for (int j = lane; j < 1024; j += 32) {
                unsigned key = __float_as_uint(Ar[j]);
                if ((key & himask) == prefix)
                    atomicAdd(&hist[(key >> (p * 8)) & 0xFF], 1);
            }
            __syncwarp();
            int part = 0;
            #pragma unroll
            for (int q2 = 0; q2 < 8; ++q2) part += hist[lane * 8 + q2];
            int scan = part;
            #pragma unroll
            for (int o = 1; o < 32; o <<= 1) {
                int vv = __shfl_up_sync(0xffffffffu, scan, o);
                if (lane >= o) scan += vv;
            }
            int excl = scan - part;
            unsigned vote = __ballot_sync(0xffffffffu, (excl <= rank) && (rank < excl + part));
            int srcl = __ffs(vote) - 1;
            int binsel = 0, nrank = 0;
            if (lane == srcl) {
                int cum = excl;
                #pragma unroll
                for (int q2 = 0; q2 < 8; ++q2) {
                    int c = hist[lane * 8 + q2];
                    if (cum + c > rank) { binsel = lane * 8 + q2; nrank = rank - cum; break; }
                    cum += c;
                }
            }
            binsel = __shfl_sync(0xffffffffu, binsel, srcl);
            rank   = __shfl_sync(0xffffffffu, nrank, srcl);
            prefix |= (unsigned)binsel << (p * 8);
            __syncwarp();
        }
        float v1 = __uint_as_float(prefix);
        int cnt = 0; unsigned mn = 0xFFFFFFFFu;
        for (int j = lane; j < 1024; j += 32) {
            unsigned key = __float_as_uint(Ar[j]);
            if (key <= prefix) cnt++; else mn = min(mn, key);
        }
        #pragma unroll
        for (int o = 16; o; o >>= 1) {
            cnt += __shfl_xor_sync(0xffffffffu, cnt, o);
            mn = min(mn, __shfl_xor_sync(0xffffffffu, mn, o));
        }
        float v2 = (cnt >= 718) ? v1 : __uint_as_float(mn);
        float delta = v1 + frac * (v2 - v1);

        float es = sEs[r];
        float m = -1e30f;
        for (int j = lane; j < 1024; j += 32) {
            if (Ar[j] > delta || j == ig) {
                float x = es + sE[j] + battn;
                float e = x > 0.f ? x : 0.01f * x;
                m = fmaxf(m, e);
            }
        }
        #pragma unroll
        for (int o = 16; o; o >>= 1) m = fmaxf(m, __shfl_xor_sync(0xffffffffu, m, o));
        float ssum = 0.f;
        for (int j = lane; j < 1024; j += 32) {
            if (Ar[j] > delta || j == ig) {
                float x = es + sE[j] + battn;
                float e = x > 0.f ? x : 0.01f * x;
                ssum += expf(e - m);
            }
        }
        ssum = wredsum(ssum);
        float inv = 1.f / ssum;
        for (int j = lane; j < 1024; j += 32) {
            bool msk = (Ar[j] > delta) || (j == ig);
            float aj = 0.f;
            if (msk) {
                float x = es + sE[j] + battn;
                float e = x > 0.f ? x : 0.01f * x;
                aj = expf(e - m) * inv;
            }
            Ar[j] = aj;
            if (aj != 0.f) sFlag[j >> 5] = 1;
        }
        __syncwarp();
    }
    __syncthreads();

    // ---- Phase D: out = alpha @ H, skipping all-zero alpha tiles ----
    int tx = tid & 15, ty = tid >> 4;
    int r0 = ty * 2, r1 = r0 + 1;
    float acc0[16], acc1[16];
    #pragma unroll
    for (int q = 0; q < 16; ++q) { acc0[q] = 0.f; acc1[q] = 0.f; }
    for (int jt = 0; jt < 32; ++jt) {
        if (sFlag[jt] == 0) continue;            // uniform across CTA
        __syncthreads();
        {
            const float4* src = (const float4*)(hb + (long)jt * 32 * HDIM);
            for (int v = tid; v < 2048; v += 256) {
                int r = v >> 6, c = v & 63;
                ((float4*)(sH + r * PPAD))[c] = src[v];
            }
        }
        __syncthreads();
        #pragma unroll 2
        for (int k = 0; k < 32; ++k) {
            float a0 = sA[r0 * 1024 + jt * 32 + k];
            float a1 = sA[r1 * 1024 + jt * 32 + k];
            const float* hr2 = sH + k * PPAD + tx * 4;
            #pragma unroll
            for (int cc = 0; cc < 4; ++cc) {
                float4 hv = *(const float4*)(hr2 + cc * 64);
                acc0[cc * 4 + 0] = fmaf(a0, hv.x, acc0[cc * 4 + 0]);
                acc0[cc * 4 + 1] = fmaf(a0, hv.y, acc0[cc * 4 + 1]);
                acc0[cc * 4 + 2] = fmaf(a0, hv.z, acc0[cc * 4 + 2]);
                acc0[cc * 4 + 3] = fmaf(a0, hv.w, acc0[cc * 4 + 3]);
                acc1[cc * 4 + 0] = fmaf(a1, hv.x, acc1[cc * 4 + 0]);
                acc1[cc * 4 + 1] = fmaf(a1, hv.y, acc1[cc * 4 + 1]);
                acc1[cc * 4 + 2] = fmaf(a1, hv.z, acc1[cc * 4 + 2]);
                acc1[cc * 4 + 3] = fmaf(a1, hv.w, acc1[cc * 4 + 3]);
            }
        }
    }
    __syncthreads();
    // reduce 32 rows -> per-column partial sums (reuse sH region)
    float* red = sH;
    #pragma unroll
    for (int cc = 0; cc < 4; ++cc)
        #pragma unroll
        for (int q = 0; q < 4; ++q) {
            int col = tx * 4 + cc * 64 + q;
            red[ty * 256 + col] = acc0[cc * 4 + q] + acc1[cc * 4 + q];
        }
    __syncthreads();
    {
        int col = tid;
        float s = 0.f;
        #pragma unroll
        for (int yy = 0; yy < 16; ++yy) s += red[yy * 256 + col];
        g_partial[((nb) * 32 + ib) * 256 + col] = s;
    }
}

// ---------------- final: means -> 3 GEMMs -> LN -> d_out ----------------
__global__ void __launch_bounds__(256) final_kernel(
    const float* __restrict__ W0, const float* __restrict__ b0,
    const float* __restrict__ W1, const float* __restrict__ b1,
    const float* __restrict__ W2, const float* __restrict__ b2,
    const float* __restrict__ g0, const float* __restrict__ be0,
    const float* __restrict__ g1, const float* __restrict__ be1,
    const float* __restrict__ g2, const float* __restrict__ be2,
    float* __restrict__ out)
{
    __shared__ float vin[1024];
    __shared__ float red[40];
    int which = blockIdx.x, b = blockIdx.y, tid = threadIdx.x;
    int K = (which == 2) ? 1024 : 512;
    int hb2 = (which == 1) ? 2 : 0;

    for (int e = tid; e < K; e += 256) {
        int n = hb2 + (e >> 8), col = e & 255;
        const float* p = g_partial + ((long)(n * 16 + b) * 32) * 256 + col;
        float s = 0.f;
        #pragma unroll
        for (int ibk = 0; ibk < 32; ++ibk) s += p[ibk * 256];
        vin[e] = s * (1.f / 1024.f);
    }
    __syncthreads();

    const float* W  = (which == 0) ? W0 : ((which == 1) ? W1 : W2);
    const float* bi = (which == 0) ? b0 : ((which == 1) ? b1 : b2);
    const float* g  = (which == 0) ? g0 : ((which == 1) ? g1 : g2);
    const float* be = (which == 0) ? be0 : ((which == 1) ? be1 : be2);

    float acc3[3];
    #pragma unroll
    for (int oi = 0; oi < 3; ++oi) {
        int o = tid + oi * 256;
        float a = bi[o];
        for (int k = 0; k < K; ++k) a = fmaf(vin[k], W[(long)k * OUTD + o], a);
        acc3[oi] = a;
    }

    float ls = acc3[0] + acc3[1] + acc3[2];
    ls = wredsum(ls);
    if ((tid & 31) == 0) red[tid >> 5] = ls;
    __syncthreads();
    if (tid == 0) {
        float s = 0.f;
        for (int q = 0; q < 8; ++q) s += red[q];
        red[32] = s * (1.f / 768.f);
    }
    __syncthreads();
    float mu = red[32];
    __syncthreads();
    float vv = 0.f;
    #pragma unroll
    for (int oi = 0; oi < 3; ++oi) { float d = acc3[oi] - mu; vv += d * d; }
    vv = wredsum(vv);
    if ((tid & 31) == 0) red[tid >> 5] = vv;
    __syncthreads();
    if (tid == 0) {
        float s = 0.f;
        for (int q = 0; q < 8; ++q) s += red[q];
        red[33] = s * (1.f / 768.f);
    }
    __syncthreads();
    float rstd = rsqrtf(red[33] + 1e-5f);
    #pragma unroll
    for (int oi = 0; oi < 3; ++oi) {
        int o = tid + oi * 256;
        out[(long)which * BB * OUTD + (long)b * OUTD + o] = (acc3[oi] - mu) * rstd * g[o] + be[o];
    }
}

// ---------------- launch ----------------
extern "C" void kernel_launch(void* const* d_in, const int* in_sizes, int n_in,
                              void* d_out, int out_size)
{
    const float* x    = (const float*)d_in[0];
    const float* Wfc  = (const float*)d_in[1];
    const float* bfc  = (const float*)d_in[2];
    const float* lng  = (const float*)d_in[3];
    const float* lnb  = (const float*)d_in[4];
    const float* adjw = (const float*)d_in[5];
    const float* Watt = (const float*)d_in[6];
    const float* batt = (const float*)d_in[7];
    const float* Wl = (const float*)d_in[8];  const float* bl = (const float*)d_in[9];
    const float* Ws = (const float*)d_in[10]; const float* bs = (const float*)d_in[11];
    const float* Wc = (const float*)d_in[12]; const float* bc = (const float*)d_in[13];
    const float* gl = (const float*)d_in[14]; const float* bel = (const float*)d_in[15];
    const float* gs = (const float*)d_in[16]; const float* bes = (const float*)d_in[17];
    const float* gc = (const float*)d_in[18]; const float* bec = (const float*)d_in[19];
    float* out = (float*)d_out;

    float *hp = nullptr, *tp = nullptr;
    cudaGetSymbolAddress((void**)&hp, g_h);
    cudaGetSymbolAddress((void**)&tp, g_t);

    // 1) h_pre = x @ Wfc + bfc  (per head)
    gemm128<<<dim3(HDIM / 128, BLROWS / 128, NHEAD), 256>>>(
        x, Wfc, bfc, hp,
        BLROWS, HDIM, DDIM,
        0L, (long)DDIM * HDIM, (long)HDIM, (long)BLROWS * HDIM);

    // 2) LN in place + e_src/e_dst
    ln_att_kernel<<<(NHEAD * BLROWS) / 8, 256>>>(lng, lnb, Watt);

    // 3) t = h @ adjw  (per head)
    gemm128<<<dim3(HDIM / 128, BLROWS / 128, NHEAD), 256>>>(
        hp, adjw, nullptr, tp,
        BLROWS, HDIM, HDIM,
        (long)BLROWS * HDIM, (long)HDIM * HDIM, 0L, (long)BLROWS * HDIM);

    // 4) fused attention
    const int smemBytes = 52416 * 4;   // ~205 KB
    cudaFuncSetAttribute(attn_kernel, cudaFuncAttributeMaxDynamicSharedMemorySize, smemBytes);
    attn_kernel<<<dim3(32, BB, NHEAD), 256, smemBytes>>>(batt);

    // 5) finals
    final_kernel<<<dim3(3, BB), 256>>>(Wl, bl, Ws, bs, Wc, bc, gl, bel, gs, bes, gc, bec, out);
}

// round 3
// speedup vs baseline: 4.2974x; 2.8908x over previous
#include <cuda_runtime.h>
#include <cuda_bf16.h>
#include <math.h>
#include <stdint.h>

#define BB     16
#define LSEQ   1024
#define DDIM   768
#define HDIM   256
#define NHEAD  4
#define OUTD   768
#define BLROWS (BB*LSEQ)          // 16384

// ---------------- scratch (device globals; no allocation) ----------------
__device__ float g_h[(size_t)NHEAD * BLROWS * HDIM];              // fp32 h (LN'ed)
__device__ __nv_bfloat16 g_hb[(size_t)NHEAD * BLROWS * HDIM];     // bf16 h
__device__ __nv_bfloat16 g_tb[(size_t)NHEAD * BLROWS * HDIM];     // bf16 t
__device__ __nv_bfloat16 g_adjwT[(size_t)NHEAD * HDIM * HDIM];    // adjw^T bf16
__device__ float g_esrc[NHEAD * BLROWS];
__device__ float g_edst[NHEAD * BLROWS];
__device__ float g_partial[NHEAD * BB * 8 * HDIM];

// ---------------- helpers ----------------
__device__ __forceinline__ float wredsum(float v) {
    #pragma unroll
    for (int o = 16; o; o >>= 1) v += __shfl_xor_sync(0xffffffffu, v, o);
    return v;
}
__device__ __forceinline__ float sigf(float x) {
    if (x >= 0.f) { float z = expf(-x); return 1.f / (1.f + z); }
    float z = expf(x); return z / (1.f + z);
}
__device__ __forceinline__ void mma16816(float c[4], const unsigned a[4], const unsigned b[2]) {
    asm volatile("mma.sync.aligned.m16n8k16.row.col.f32.bf16.bf16.f32 "
        "{%0,%1,%2,%3}, {%4,%5,%6,%7}, {%8,%9}, {%0,%1,%2,%3};"
        : "+f"(c[0]), "+f"(c[1]), "+f"(c[2]), "+f"(c[3])
        : "r"(a[0]), "r"(a[1]), "r"(a[2]), "r"(a[3]), "r"(b[0]), "r"(b[1]));
}

// ---------------- SGEMM 128x128, 8x8 microtiles (fp32, stage 1) ----------
__global__ void __launch_bounds__(256, 2) gemm128(
    const float* __restrict__ A, const float* __restrict__ Bm,
    const float* __restrict__ bias, float* __restrict__ C,
    int M, int N, int K,
    long aStride, long bStride, long biasStride, long cStride)
{
    int z = blockIdx.z;
    A += (long)z * aStride;
    Bm += (long)z * bStride;
    C += (long)z * cStride;
    if (bias) bias += (long)z * biasStride;

    __shared__ float Ast[16 * 128];
    __shared__ float Bs[16 * 128];

    int m0 = blockIdx.y * 128, n0 = blockIdx.x * 128;
    int tid = threadIdx.x;
    int rowg = (tid & 3) + ((tid >> 6) << 2);
    int colg = (tid >> 2) & 15;

    float acc[8][8];
    #pragma unroll
    for (int i = 0; i < 8; ++i)
        #pragma unroll
        for (int j = 0; j < 8; ++j) acc[i][j] = 0.f;

    for (int k0 = 0; k0 < K; k0 += 16) {
        __syncthreads();
        #pragma unroll
        for (int q = 0; q < 2; ++q) {
            int idx = tid + q * 256;
            int row = idx >> 2, k4 = idx & 3;
            float4 v = *(const float4*)&A[(long)(m0 + row) * K + k0 + k4 * 4];
            int k = k4 * 4;
            Ast[(k + 0) * 128 + row] = v.x;
            Ast[(k + 1) * 128 + row] = v.y;
            Ast[(k + 2) * 128 + row] = v.z;
            Ast[(k + 3) * 128 + row] = v.w;
        }
        #pragma unroll
        for (int q = 0; q < 2; ++q) {
            int idx = tid + q * 256;
            int kr = idx >> 5, n4 = idx & 31;
            *(float4*)&Bs[kr * 128 + n4 * 4] =
                *(const float4*)&Bm[(long)(k0 + kr) * N + n0 + n4 * 4];
        }
        __syncthreads();
        #pragma unroll
        for (int k = 0; k < 16; ++k) {
            float ar[8], bc[8];
            *(float4*)&ar[0] = *(const float4*)&Ast[k * 128 + rowg * 8];
            *(float4*)&ar[4] = *(const float4*)&Ast[k * 128 + rowg * 8 + 4];
            *(float4*)&bc[0] = *(const float4*)&Bs[k * 128 + colg * 8];
            *(float4*)&bc[4] = *(const float4*)&Bs[k * 128 + colg * 8 + 4];
            #pragma unroll
            for (int i = 0; i < 8; ++i)
                #pragma unroll
                for (int j = 0; j < 8; ++j)
                    acc[i][j] = fmaf(ar[i], bc[j], acc[i][j]);
        }
    }
    #pragma unroll
    for (int i = 0; i < 8; ++i) {
        int r = m0 + rowg * 8 + i;
        #pragma unroll
        for (int jj = 0; jj < 2; ++jj) {
            int c = n0 + colg * 8 + jj * 4;
            float4 o;
            o.x = acc[i][jj * 4 + 0]; o.y = acc[i][jj * 4 + 1];
            o.z = acc[i][jj * 4 + 2]; o.w = acc[i][jj * 4 + 3];
            if (bias) {
                const float* bp = &bias[c];
                o.x += bp[0]; o.y += bp[1]; o.z += bp[2]; o.w += bp[3];
            }
            *(float4*)&C[(long)r * N + c] = o;
        }
    }
}

// ---------------- LN in place + e_src/e_dst + bf16 copy of h ----------
__global__ void __launch_bounds__(256) ln_att_kernel(
    const float* __restrict__ lng, const float* __restrict__ lnb,
    const float* __restrict__ Watt)
{
    int row  = blockIdx.x * 8 + (threadIdx.x >> 5);
    int lane = threadIdx.x & 31;
    int n = row >> 14;
    float* hr = g_h + (long)row * HDIM;
    __nv_bfloat16* hbr = g_hb + (long)row * HDIM;

    float v[8];
    #pragma unroll
    for (int q = 0; q < 8; ++q) v[q] = hr[q * 32 + lane];

    float s = 0.f;
    #pragma unroll
    for (int q = 0; q < 8; ++q) s += v[q];
    s = wredsum(s);
    float mu = s * (1.f / 256.f);

    float s2 = 0.f;
    #pragma unroll
    for (int q = 0; q < 8; ++q) { float d = v[q] - mu; s2 += d * d; }
    s2 = wredsum(s2);
    float rstd = rsqrtf(s2 * (1.f / 256.f) + 1e-5f);

    const float* g  = lng + n * HDIM;
    const float* bb = lnb + n * HDIM;
    const float* ws = Watt + n * 2 * HDIM;
    const float* wd = ws + HDIM;

    float a1 = 0.f, a2 = 0.f;
    #pragma unroll
    for (int q = 0; q < 8; ++q) {
        int c = q * 32 + lane;
        float o = (v[q] - mu) * rstd * g[c] + bb[c];
        hr[c] = o;
        hbr[c] = __float2bfloat16(o);
        a1 = fmaf(o, ws[c], a1);
        a2 = fmaf(o, wd[c], a2);
    }
    a1 = wredsum(a1);
    a2 = wredsum(a2);
    if (lane == 0) { g_esrc[row] = a1; g_edst[row] = a2; }
}

// ---------------- adjw transpose to bf16 ----------------
__global__ void adjwT_kernel(const float* __restrict__ adjw)
{
    int e = blockIdx.x, n = blockIdx.y, d = threadIdx.x;
    g_adjwT[((long)n * HDIM + e) * HDIM + d] =
        __float2bfloat16(adjw[((long)n * HDIM + d) * HDIM + e]);
}

// ---------------- tb = hb @ adjw (bf16 tensor GEMM) ----------------
// grid (BLROWS/128, NHEAD); block 256
__global__ void __launch_bounds__(256, 2) tb_gemm_kernel()
{
    extern __shared__ char smraw[];
    __nv_bfloat16* sA = (__nv_bfloat16*)smraw;   // 128 x 264
    __nv_bfloat16* sB = sA + 128 * 264;          // 64 x 264

    int mb = blockIdx.x, n = blockIdx.y;
    int tid = threadIdx.x, lane = tid & 31, w = tid >> 5;
    int gr = lane >> 2, qp = lane & 3;
    long rbase = (long)n * BLROWS + (long)mb * 128;
    const __nv_bfloat16* asrc = g_hb + rbase * HDIM;

    for (int idx = tid; idx < 128 * 32; idx += 256) {
        int r = idx >> 5, k8 = idx & 31;
        *(float4*)&sA[r * 264 + k8 * 8] = *(const float4*)&asrc[(long)r * HDIM + k8 * 8];
    }
    __syncthreads();

    unsigned Afrag[16][4];
    {
        const __nv_bfloat16* a0 = sA + (w * 16 + gr) * 264;
        const __nv_bfloat16* a1 = a0 + 8 * 264;
        #pragma unroll
        for (int kt = 0; kt < 16; ++kt) {
            int c = kt * 16 + qp * 2;
            Afrag[kt][0] = *(const unsigned*)(a0 + c);
            Afrag[kt][1] = *(const unsigned*)(a1 + c);
            Afrag[kt][2] = *(const unsigned*)(a0 + c + 8);
            Afrag[kt][3] = *(const unsigned*)(a1 + c + 8);
        }
    }

    __nv_bfloat16* outp = g_tb + rbase * HDIM;
    for (int ec = 0; ec < 4; ++ec) {
        __syncthreads();
        const __nv_bfloat16* bsrc = g_adjwT + ((long)n * HDIM + ec * 64) * HDIM;
        for (int idx = tid; idx < 64 * 32; idx += 256) {
            int r = idx >> 5, k8 = idx & 31;
            *(float4*)&sB[r * 264 + k8 * 8] = *(const float4*)&bsrc[(long)r * HDIM + k8 * 8];
        }
        __syncthreads();
        #pragma unroll
        for (int nt = 0; nt < 8; ++nt) {
            float c[4] = {0.f, 0.f, 0.f, 0.f};
            const __nv_bfloat16* brow = sB + (nt * 8 + gr) * 264 + qp * 2;
            #pragma unroll
            for (int kt = 0; kt < 16; ++kt) {
                unsigned bf[2];
                bf[0] = *(const unsigned*)(brow + kt * 16);
                bf[1] = *(const unsigned*)(brow + kt * 16 + 8);
                mma16816(c, Afrag[kt], bf);
            }
            int col = ec * 64 + nt * 8 + qp * 2;
            int row = w * 16 + gr;
            *(__nv_bfloat162*)&outp[(long)row * HDIM + col] = __floats2bfloat162_rn(c[0], c[1]);
            *(__nv_bfloat162*)&outp[(long)(row + 8) * HDIM + col] = __floats2bfloat162_rn(c[2], c[3]);
        }
    }
}

// ---------------- attention: tensor-core counting + exact fallback ------
// grid (8, BB, NHEAD); block 256
#define TH_HI 33.4f
__global__ void __launch_bounds__(256, 2) attn_count_kernel(
    const float* __restrict__ adjw, const float* __restrict__ batt)
{
    extern __shared__ char smraw[];
    __nv_bfloat16* sT  = (__nv_bfloat16*)smraw;    // 128 x 264
    __nv_bfloat16* sB  = sT + 128 * 264;           // 64 x 264 (reused as scratch)
    float* sCol = (float*)(sB + 64 * 264);         // 256
    int*   sCnt = (int*)(sCol + 256);              // 128

    int mb = blockIdx.x, b = blockIdx.y, n = blockIdx.z;
    int tid = threadIdx.x, lane = tid & 31, w = tid >> 5;
    int gr = lane >> 2, qp = lane & 3;
    long nb = (long)(n * 16 + b);
    long base = nb * LSEQ * HDIM;
    int r0 = mb * 128;
    int erow0 = n * BLROWS + b * LSEQ;
    const __nv_bfloat16* hbp = g_hb + base;
    const __nv_bfloat16* tbp = g_tb + base + (long)r0 * HDIM;

    // load T rows (bf16)
    for (int idx = tid; idx < 128 * 32; idx += 256) {
        int r = idx >> 5, k8 = idx & 31;
        *(float4*)&sT[r * 264 + k8 * 8] = *(const float4*)&tbp[(long)r * HDIM + k8 * 8];
    }
    __syncthreads();

    unsigned Afrag[16][4];
    {
        const __nv_bfloat16* a0 = sT + (w * 16 + gr) * 264;
        const __nv_bfloat16* a1 = a0 + 8 * 264;
        #pragma unroll
        for (int kt = 0; kt < 16; ++kt) {
            int c = kt * 16 + qp * 2;
            Afrag[kt][0] = *(const unsigned*)(a0 + c);
            Afrag[kt][1] = *(const unsigned*)(a1 + c);
            Afrag[kt][2] = *(const unsigned*)(a0 + c + 8);
            Afrag[kt][3] = *(const unsigned*)(a1 + c + 8);
        }
    }

    int cntA = 0, cntB = 0;
    for (int jc = 0; jc < 16; ++jc) {
        __syncthreads();
        const __nv_bfloat16* bsrc = hbp + (long)jc * 64 * HDIM;
        for (int idx = tid; idx < 64 * 32; idx += 256) {
            int r = idx >> 5, k8 = idx & 31;
            *(float4*)&sB[r * 264 + k8 * 8] = *(const float4*)&bsrc[(long)r * HDIM + k8 * 8];
        }
        __syncthreads();
        #pragma unroll
        for (int nt = 0; nt < 8; ++nt) {
            float c[4] = {0.f, 0.f, 0.f, 0.f};
            const __nv_bfloat16* brow = sB + (nt * 8 + gr) * 264 + qp * 2;
            #pragma unroll
            for (int kt = 0; kt < 16; ++kt) {
                unsigned bf[2];
                bf[0] = *(const unsigned*)(brow + kt * 16);
                bf[1] = *(const unsigned*)(brow + kt * 16 + 8);
                mma16816(c, Afrag[kt], bf);
            }
            cntA += (c[0] > TH_HI) + (c[1] > TH_HI);
            cntB += (c[2] > TH_HI) + (c[3] > TH_HI);
        }
    }
    cntA += __shfl_xor_sync(0xffffffffu, cntA, 1);
    cntA += __shfl_xor_sync(0xffffffffu, cntA, 2);
    cntB += __shfl_xor_sync(0xffffffffu, cntB, 1);
    cntB += __shfl_xor_sync(0xffffffffu, cntB, 2);
    if ((lane & 3) == 0) {
        sCnt[w * 16 + gr] = cntA;
        sCnt[w * 16 + gr + 8] = cntB;
    }
    __syncthreads();

    // column sums of h (fp32) over this CTA's 128 rows
    const float* hfp = g_h + base + (long)r0 * HDIM;
    {
        float cs = 0.f;
        for (int r = 0; r < 128; ++r) cs += hfp[(long)r * HDIM + tid];
        sCol[tid] = cs;
    }
    __syncthreads();

    // exact fallback for uncertain rows (statistically never taken)
    float battn = batt[n];
    for (int r = 0; r < 128; ++r) {
        if (sCnt[r] >= 308) continue;       // provably >=308 exact ones -> out_i = h_i

        float* tI   = (float*)sB;           // 256
        float* Srow = tI + 256;             // 1024
        int*   hist = (int*)(Srow + 1024);  // 256
        int*   iv   = hist + 256;           // misc

        int gi = r0 + r;
        const float* hrow = g_h + base + (long)gi * HDIM;
        const float* aw = adjw + (long)n * HDIM * HDIM;

        {   // exact t_i (fp32)
            float acc = 0.f;
            for (int d = 0; d < 256; ++d) acc = fmaf(hrow[d], aw[d * 256 + tid], acc);
            tI[tid] = acc;
        }
        __syncthreads();
        for (int j = tid; j < 1024; j += 256) {   // exact sigmoid(S) row
            const float* hj = g_h + base + (long)j * HDIM;
            float s = 0.f;
            for (int k = 0; k < 256; ++k) s = fmaf(tI[k], hj[k], s);
            Srow[j] = sigf(s);
        }
        if (tid == 0) iv[0] = 0;
        __syncthreads();
        {
            int c1 = 0;
            for (int j = tid; j < 1024; j += 256) c1 += (Srow[j] >= 1.0f);
            atomicAdd(&iv[0], c1);
        }
        __syncthreads();
        int cnt1 = iv[0];
        if (cnt1 >= 308) { __syncthreads(); continue; }

        if (w == 0) {   // exact radix-select quantile + masked softmax (warp 0)
            unsigned prefix = 0; int rank = 716;
            for (int p = 3; p >= 0; --p) {
                for (int q2 = lane; q2 < 256; q2 += 32) hist[q2] = 0;
                __syncwarp();
                unsigned himask = (p == 3) ? 0u : (0xFFFFFFFFu << ((p + 1) * 8));
                for (int j = lane; j < 1024; j += 32) {
                    unsigned key = __float_as_uint(Srow[j]);
                    if ((key & himask) == prefix)
                        atomicAdd(&hist[(key >> (p * 8)) & 0xFF], 1);
                }
                __syncwarp();
                int part = 0;
                #pragma unroll
                for (int q2 = 0; q2 < 8; ++q2) part += hist[lane * 8 + q2];
                int scan = part;
                #pragma unroll
                for (int o = 1; o < 32; o <<= 1) {
                    int vv = __shfl_up_sync(0xffffffffu, scan, o);
                    if (lane >= o) scan += vv;
                }
                int excl = scan - part;
                unsigned vote = __ballot_sync(0xffffffffu, (excl <= rank) && (rank < excl + part));
                int srcl = __ffs(vote) - 1;
                int binsel = 0, nrank = 0;
                if (lane == srcl) {
                    int cum = excl;
                    #pragma unroll
                    for (int q2 = 0; q2 < 8; ++q2) {
                        int c = hist[lane * 8 + q2];
                        if (cum + c > rank) { binsel = lane * 8 + q2; nrank = rank - cum; break; }
                        cum += c;
                    }
                }
                binsel = __shfl_sync(0xffffffffu, binsel, srcl);
                rank   = __shfl_sync(0xffffffffu, nrank, srcl);
                prefix |= (unsigned)binsel << (p * 8);
                __syncwarp();
            }
            float v1 = __uint_as_float(prefix);
            int cnt = 0; unsigned mn = 0xFFFFFFFFu;
            for (int j = lane; j < 1024; j += 32) {
                unsigned key = __float_as_uint(Srow[j]);
                if (key <= prefix) cnt++; else mn = min(mn, key);
            }
            #pragma unroll
            for (int o = 16; o; o >>= 1) {
                cnt += __shfl_xor_sync(0xffffffffu, cnt, o);
                mn = min(mn, __shfl_xor_sync(0xffffffffu, mn, o));
            }
            float v2 = (cnt >= 718) ? v1 : __uint_as_float(mn);
            const float frac = (float)(0.7 * 1023.0 - 716.0);
            float delta = v1 + frac * (v2 - v1);

            float es = g_esrc[erow0 + gi];
            float m = -1e30f;
            for (int j = lane; j < 1024; j += 32) {
                if (Srow[j] > delta || j == gi) {
                    float x = es + g_edst[erow0 + j] + battn;
                    float e = x > 0.f ? x : 0.01f * x;
                    m = fmaxf(m, e);
                }
            }
            #pragma unroll
            for (int o = 16; o; o >>= 1) m = fmaxf(m, __shfl_xor_sync(0xffffffffu, m, o));
            float ssum = 0.f;
            for (int j = lane; j < 1024; j += 32) {
                if (Srow[j] > delta || j == gi) {
                    float x = es + g_edst[erow0 + j] + battn;
                    float e = x > 0.f ? x : 0.01f * x;
                    ssum += expf(e - m);
                }
            }
            ssum = wredsum(ssum);
            float inv = 1.f / ssum;
            for (int j = lane; j < 1024; j += 32) {
                bool msk = (Srow[j] > delta) || (j == gi);
                float aj = 0.f;
                if (msk) {
                    float x = es + g_edst[erow0 + j] + battn;
                    float e = x > 0.f ? x : 0.01f * x;
                    aj = expf(e - m) * inv;
                }
                Srow[j] = aj;
            }
        }
        __syncthreads();
        {   // colsum adjust: += alpha@H - h_i
            float acc = 0.f;
            for (int j = 0; j < 1024; ++j)
                acc = fmaf(Srow[j], g_h[base + (long)j * HDIM + tid], acc);
            sCol[tid] += acc - hrow[tid];
        }
        __syncthreads();
    }

    g_partial[(nb * 8 + mb) * 256 + tid] = sCol[tid];
}

// ---------------- final: means -> 3 GEMMs -> LN -> d_out ----------------
__global__ void __launch_bounds__(256) final_kernel(
    const float* __restrict__ W0, const float* __restrict__ b0,
    const float* __restrict__ W1, const float* __restrict__ b1,
    const float* __restrict__ W2, const float* __restrict__ b2,
    const float* __restrict__ g0, const float* __restrict__ be0,
    const float* __restrict__ g1, const float* __restrict__ be1,
    const float* __restrict__ g2, const float* __restrict__ be2,
    float* __restrict__ out)
{
    __shared__ float vin[1024];
    __shared__ float red[40];
    int which = blockIdx.x, b = blockIdx.y, tid = threadIdx.x;
    int K = (which == 2) ? 1024 : 512;
    int hb2 = (which == 1) ? 2 : 0;

    for (int e = tid; e < K; e += 256) {
        int n = hb2 + (e >> 8), col = e & 255;
        const float* p = g_partial + ((long)(n * 16 + b) * 8) * 256 + col;
        float s = 0.f;
        #pragma unroll
        for (int ibk = 0; ibk < 8; ++ibk) s += p[ibk * 256];
        vin[e] = s * (1.f / 1024.f);
    }
    __syncthreads();

    const float* W  = (which == 0) ? W0 : ((which == 1) ? W1 : W2);
    const float* bi = (which == 0) ? b0 : ((which == 1) ? b1 : b2);
    const float* g  = (which == 0) ? g0 : ((which == 1) ? g1 : g2);
    const float* be = (which == 0) ? be0 : ((which == 1) ? be1 : be2);

    float acc3[3];
    #pragma unroll
    for (int oi = 0; oi < 3; ++oi) {
        int o = tid + oi * 256;
        float a = bi[o];
        for (int k = 0; k < K; ++k) a = fmaf(vin[k], W[(long)k * OUTD + o], a);
        acc3[oi] = a;
    }

    float ls = acc3[0] + acc3[1] + acc3[2];
    ls = wredsum(ls);
    if ((tid & 31) == 0) red[tid >> 5] = ls;
    __syncthreads();
    if (tid == 0) {
        float s = 0.f;
        for (int q = 0; q < 8; ++q) s += red[q];
        red[32] = s * (1.f / 768.f);
    }
    __syncthreads();
    float mu = red[32];
    __syncthreads();
    float vv = 0.f;
    #pragma unroll
    for (int oi = 0; oi < 3; ++oi) { float d = acc3[oi] - mu; vv += d * d; }
    vv = wredsum(vv);
    if ((tid & 31) == 0) red[tid >> 5] = vv;
    __syncthreads();
    if (tid == 0) {
        float s = 0.f;
        for (int q = 0; q < 8; ++q) s += red[q];
        red[33] = s * (1.f / 768.f);
    }
    __syncthreads();
    float rstd = rsqrtf(red[33] + 1e-5f);
    #pragma unroll
    for (int oi = 0; oi < 3; ++oi) {
        int o = tid + oi * 256;
        out[(long)which * BB * OUTD + (long)b * OUTD + o] = (acc3[oi] - mu) * rstd * g[o] + be[o];
    }
}

// ---------------- launch ----------------
extern "C" void kernel_launch(void* const* d_in, const int* in_sizes, int n_in,
                              void* d_out, int out_size)
{
    const float* x    = (const float*)d_in[0];
    const float* Wfc  = (const float*)d_in[1];
    const float* bfc  = (const float*)d_in[2];
    const float* lng  = (const float*)d_in[3];
    const float* lnb  = (const float*)d_in[4];
    const float* adjw = (const float*)d_in[5];
    const float* Watt = (const float*)d_in[6];
    const float* batt = (const float*)d_in[7];
    const float* Wl = (const float*)d_in[8];  const float* bl = (const float*)d_in[9];
    const float* Ws = (const float*)d_in[10]; const float* bs = (const float*)d_in[11];
    const float* Wc = (const float*)d_in[12]; const float* bc = (const float*)d_in[13];
    const float* gl = (const float*)d_in[14]; const float* bel = (const float*)d_in[15];
    const float* gs = (const float*)d_in[16]; const float* bes = (const float*)d_in[17];
    const float* gc = (const float*)d_in[18]; const float* bec = (const float*)d_in[19];
    float* out = (float*)d_out;

    float* hp = nullptr;
    cudaGetSymbolAddress((void**)&hp, g_h);

    // 0) adjw^T bf16 (independent)
    adjwT_kernel<<<dim3(HDIM, NHEAD), 256>>>(adjw);

    // 1) h_pre = x @ Wfc + bfc (fp32)
    gemm128<<<dim3(HDIM / 128, BLROWS / 128, NHEAD), 256>>>(
        x, Wfc, bfc, hp,
        BLROWS, HDIM, DDIM,
        0L, (long)DDIM * HDIM, (long)HDIM, (long)BLROWS * HDIM);

    // 2) LN in place + e_src/e_dst + bf16 h
    ln_att_kernel<<<(NHEAD * BLROWS) / 8, 256>>>(lng, lnb, Watt);

    // 3) tb = hb @ adjw (bf16 tensor)
    const int smemTB = (128 * 264 + 64 * 264) * 2;
    cudaFuncSetAttribute(tb_gemm_kernel, cudaFuncAttributeMaxDynamicSharedMemorySize, smemTB);
    tb_gemm_kernel<<<dim3(BLROWS / 128, NHEAD), 256, smemTB>>>();

    // 4) attention counting + fallback + partial means
    const int smemAT = (128 * 264 + 64 * 264) * 2 + 256 * 4 + 128 * 4 + 64;
    cudaFuncSetAttribute(attn_count_kernel, cudaFuncAttributeMaxDynamicSharedMemorySize, smemAT);
    attn_count_kernel<<<dim3(8, BB, NHEAD), 256, smemAT>>>(adjw, batt);

    // 5) finals
    final_kernel<<<dim3(3, BB), 256>>>(Wl, bl, Ws, bs, Wc, bc, gl, bel, gs, bes, gc, bec, out);
}

// round 4
// speedup vs baseline: 6.1884x; 1.4400x over previous
#include <cuda_runtime.h>
#include <cuda_bf16.h>
#include <math.h>
#include <stdint.h>

#define BB     16
#define LSEQ   1024
#define DDIM   768
#define HDIM   256
#define NHEAD  4
#define OUTD   768
#define BLROWS (BB*LSEQ)          // 16384

// ---------------- scratch (device globals; no allocation) ----------------
__device__ float g_h[(size_t)NHEAD * BLROWS * HDIM];              // fp32 h
__device__ __nv_bfloat16 g_hb[(size_t)NHEAD * BLROWS * HDIM];     // bf16 h
__device__ __nv_bfloat16 g_tb[(size_t)NHEAD * BLROWS * HDIM];     // bf16 t
__device__ __nv_bfloat16 g_adjwT[(size_t)NHEAD * HDIM * HDIM];    // adjw^T bf16
__device__ __nv_bfloat16 g_xhi[(size_t)BLROWS * DDIM];
__device__ __nv_bfloat16 g_xlo[(size_t)BLROWS * DDIM];
__device__ __nv_bfloat16 g_WThi[(size_t)NHEAD * HDIM * DDIM];     // Wfc^T hi
__device__ __nv_bfloat16 g_WTlo[(size_t)NHEAD * HDIM * DDIM];     // Wfc^T lo
__device__ float g_esrc[NHEAD * BLROWS];
__device__ float g_edst[NHEAD * BLROWS];
__device__ float g_partial[NHEAD * BB * 8 * HDIM];

// ---------------- helpers ----------------
__device__ __forceinline__ float wredsum(float v) {
    #pragma unroll
    for (int o = 16; o; o >>= 1) v += __shfl_xor_sync(0xffffffffu, v, o);
    return v;
}
__device__ __forceinline__ float sigf(float x) {
    if (x >= 0.f) { float z = expf(-x); return 1.f / (1.f + z); }
    float z = expf(x); return z / (1.f + z);
}
__device__ __forceinline__ void mma16816(float c[4], const unsigned a[4], const unsigned b[2]) {
    asm volatile("mma.sync.aligned.m16n8k16.row.col.f32.bf16.bf16.f32 "
        "{%0,%1,%2,%3}, {%4,%5,%6,%7}, {%8,%9}, {%0,%1,%2,%3};"
        : "+f"(c[0]), "+f"(c[1]), "+f"(c[2]), "+f"(c[3])
        : "r"(a[0]), "r"(a[1]), "r"(a[2]), "r"(a[3]), "r"(b[0]), "r"(b[1]));
}
__device__ __forceinline__ void ldsm4(unsigned r[4], unsigned addr) {
    asm volatile("ldmatrix.sync.aligned.m8n8.x4.shared.b16 {%0,%1,%2,%3}, [%4];"
        : "=r"(r[0]), "=r"(r[1]), "=r"(r[2]), "=r"(r[3]) : "r"(addr));
}
__device__ __forceinline__ unsigned sptr(const void* p) {
    return (unsigned)__cvta_generic_to_shared(p);
}

// ---------------- prep: split x into bf16 hi/lo ----------------
__global__ void split_x_kernel(const float* __restrict__ x)
{
    long i = (long)blockIdx.x * 1024 + threadIdx.x * 4;
    float4 v = *(const float4*)(x + i);
    __nv_bfloat16 h0 = __float2bfloat16(v.x);
    __nv_bfloat16 h1 = __float2bfloat16(v.y);
    __nv_bfloat16 h2 = __float2bfloat16(v.z);
    __nv_bfloat16 h3 = __float2bfloat16(v.w);
    __nv_bfloat162* ph = (__nv_bfloat162*)&g_xhi[i];
    ph[0] = __nv_bfloat162(h0, h1);
    ph[1] = __nv_bfloat162(h2, h3);
    __nv_bfloat162* pl = (__nv_bfloat162*)&g_xlo[i];
    pl[0] = __nv_bfloat162(__float2bfloat16(v.x - __bfloat162float(h0)),
                           __float2bfloat16(v.y - __bfloat162float(h1)));
    pl[1] = __nv_bfloat162(__float2bfloat16(v.z - __bfloat162float(h2)),
                           __float2bfloat16(v.w - __bfloat162float(h3)));
}

// ---------------- prep: Wfc^T split (grid: (HDIM e, NHEAD)) ----------------
__global__ void split_W_kernel(const float* __restrict__ Wfc)
{
    int e = blockIdx.x, n = blockIdx.y;
    long obase = ((long)n * HDIM + e) * DDIM;
    for (int d = threadIdx.x; d < DDIM; d += 256) {
        float v = Wfc[((long)n * DDIM + d) * HDIM + e];
        __nv_bfloat16 h = __float2bfloat16(v);
        g_WThi[obase + d] = h;
        g_WTlo[obase + d] = __float2bfloat16(v - __bfloat162float(h));
    }
}

// ---------------- prep: adjw transpose to bf16 ----------------
__global__ void adjwT_kernel(const float* __restrict__ adjw)
{
    int e = blockIdx.x, n = blockIdx.y, d = threadIdx.x;
    g_adjwT[((long)n * HDIM + e) * HDIM + d] =
        __float2bfloat16(adjw[((long)n * HDIM + d) * HDIM + e]);
}

// ---------------- stage 1: h_pre = x @ Wfc + bfc (bf16-split tensor) ----
// grid (8 nblk, 128 mblk); block 256 = 8 warps (2x4), warp tile 64x32
__global__ void __launch_bounds__(256) fc_gemm_kernel(const float* __restrict__ bfc)
{
    __shared__ __nv_bfloat16 sAh[128 * 40], sAl[128 * 40];
    __shared__ __nv_bfloat16 sBh[128 * 40], sBl[128 * 40];

    int nblk = blockIdx.x, mblk = blockIdx.y;
    int head = nblk >> 1, e0 = (nblk & 1) * 128;
    int m0 = mblk * 128;
    int tid = threadIdx.x, lane = tid & 31, w = tid >> 5;
    int wr = w >> 2, wc = w & 3;

    const __nv_bfloat16* Ah = g_xhi + (long)m0 * DDIM;
    const __nv_bfloat16* Al = g_xlo + (long)m0 * DDIM;
    const __nv_bfloat16* Bh = g_WThi + ((long)head * HDIM + e0) * DDIM;
    const __nv_bfloat16* Bl = g_WTlo + ((long)head * HDIM + e0) * DDIM;

    float c[4][4][4];
    #pragma unroll
    for (int i = 0; i < 4; ++i)
        #pragma unroll
        for (int j = 0; j < 4; ++j)
            #pragma unroll
            for (int q = 0; q < 4; ++q) c[i][j][q] = 0.f;

    // ldmatrix lane bases
    int aRow = wr * 64 + (lane & 7) + ((lane >> 3) & 1) * 8;
    int aK   = (lane >> 4) * 8;
    int bRow = wc * 32 + (lane & 7) + ((lane >> 4)) * 8;
    int bK   = ((lane >> 3) & 1) * 8;
    unsigned aAH = sptr(sAh) + ((aRow * 40 + aK) << 1);
    unsigned aAL = sptr(sAl) + ((aRow * 40 + aK) << 1);
    unsigned bAH = sptr(sBh) + ((bRow * 40 + bK) << 1);
    unsigned bAL = sptr(sBl) + ((bRow * 40 + bK) << 1);

    for (int kc = 0; kc < 24; ++kc) {
        int k0 = kc * 32;
        __syncthreads();
        #pragma unroll
        for (int q = 0; q < 2; ++q) {
            int idx = tid + q * 256;
            int row = idx >> 2, part = idx & 3;
            *(float4*)&sAh[row * 40 + part * 8] = *(const float4*)&Ah[(long)row * DDIM + k0 + part * 8];
            *(float4*)&sAl[row * 40 + part * 8] = *(const float4*)&Al[(long)row * DDIM + k0 + part * 8];
            *(float4*)&sBh[row * 40 + part * 8] = *(const float4*)&Bh[(long)row * DDIM + k0 + part * 8];
            *(float4*)&sBl[row * 40 + part * 8] = *(const float4*)&Bl[(long)row * DDIM + k0 + part * 8];
        }
        __syncthreads();
        #pragma unroll
        for (int ks = 0; ks < 32; ks += 16) {
            unsigned ah[4][4], al[4][4], bh[2][4], bl[2][4];
            #pragma unroll
            for (int mt = 0; mt < 4; ++mt) {
                ldsm4(ah[mt], aAH + ((mt * 16 * 40 + ks) << 1));
                ldsm4(al[mt], aAL + ((mt * 16 * 40 + ks) << 1));
            }
            #pragma unroll
            for (int p = 0; p < 2; ++p) {
                ldsm4(bh[p], bAH + ((p * 16 * 40 + ks) << 1));
                ldsm4(bl[p], bAL + ((p * 16 * 40 + ks) << 1));
            }
            #pragma unroll
            for (int mt = 0; mt < 4; ++mt)
                #pragma unroll
                for (int nt = 0; nt < 4; ++nt) {
                    const unsigned* bhp = &bh[nt >> 1][(nt & 1) * 2];
                    const unsigned* blp = &bl[nt >> 1][(nt & 1) * 2];
                    mma16816(c[mt][nt], ah[mt], bhp);
                    mma16816(c[mt][nt], ah[mt], blp);
                    mma16816(c[mt][nt], al[mt], bhp);
                }
        }
    }

    const float* bias = bfc + head * HDIM;
    #pragma unroll
    for (int mt = 0; mt < 4; ++mt)
        #pragma unroll
        for (int nt = 0; nt < 4; ++nt) {
            int row = m0 + wr * 64 + mt * 16 + (lane >> 2);
            int col = e0 + wc * 32 + nt * 8 + (lane & 3) * 2;
            float b0 = bias[col], b1 = bias[col + 1];
            float* o0 = g_h + ((long)head * BLROWS + row) * HDIM + col;
            float* o1 = o0 + 8 * HDIM;
            *(float2*)o0 = make_float2(c[mt][nt][0] + b0, c[mt][nt][1] + b1);
            *(float2*)o1 = make_float2(c[mt][nt][2] + b0, c[mt][nt][3] + b1);
        }
}

// ---------------- LN in place + e_src/e_dst + bf16 copy of h ----------
__global__ void __launch_bounds__(256) ln_att_kernel(
    const float* __restrict__ lng, const float* __restrict__ lnb,
    const float* __restrict__ Watt)
{
    int row  = blockIdx.x * 8 + (threadIdx.x >> 5);
    int lane = threadIdx.x & 31;
    int n = row >> 14;
    float* hr = g_h + (long)row * HDIM;
    __nv_bfloat16* hbr = g_hb + (long)row * HDIM;

    float v[8];
    #pragma unroll
    for (int q = 0; q < 8; ++q) v[q] = hr[q * 32 + lane];

    float s = 0.f;
    #pragma unroll
    for (int q = 0; q < 8; ++q) s += v[q];
    s = wredsum(s);
    float mu = s * (1.f / 256.f);

    float s2 = 0.f;
    #pragma unroll
    for (int q = 0; q < 8; ++q) { float d = v[q] - mu; s2 += d * d; }
    s2 = wredsum(s2);
    float rstd = rsqrtf(s2 * (1.f / 256.f) + 1e-5f);

    const float* g  = lng + n * HDIM;
    const float* bb = lnb + n * HDIM;
    const float* ws = Watt + n * 2 * HDIM;
    const float* wd = ws + HDIM;

    float a1 = 0.f, a2 = 0.f;
    #pragma unroll
    for (int q = 0; q < 8; ++q) {
        int c = q * 32 + lane;
        float o = (v[q] - mu) * rstd * g[c] + bb[c];
        hr[c] = o;
        hbr[c] = __float2bfloat16(o);
        a1 = fmaf(o, ws[c], a1);
        a2 = fmaf(o, wd[c], a2);
    }
    a1 = wredsum(a1);
    a2 = wredsum(a2);
    if (lane == 0) { g_esrc[row] = a1; g_edst[row] = a2; }
}

// ---------------- tb = hb @ adjw (bf16 tensor GEMM) ----------------
__global__ void __launch_bounds__(256, 2) tb_gemm_kernel()
{
    extern __shared__ char smraw[];
    __nv_bfloat16* sA = (__nv_bfloat16*)smraw;   // 128 x 264
    __nv_bfloat16* sB = sA + 128 * 264;          // 64 x 264

    int mb = blockIdx.x, n = blockIdx.y;
    int tid = threadIdx.x, lane = tid & 31, w = tid >> 5;
    int gr = lane >> 2, qp = lane & 3;
    long rbase = (long)n * BLROWS + (long)mb * 128;
    const __nv_bfloat16* asrc = g_hb + rbase * HDIM;

    for (int idx = tid; idx < 128 * 32; idx += 256) {
        int r = idx >> 5, k8 = idx & 31;
        *(float4*)&sA[r * 264 + k8 * 8] = *(const float4*)&asrc[(long)r * HDIM + k8 * 8];
    }
    __syncthreads();

    unsigned Afrag[16][4];
    {
        int aRow = w * 16 + (lane & 7) + ((lane >> 3) & 1) * 8;
        int aK = (lane >> 4) * 8;
        unsigned aA = sptr(sA) + ((aRow * 264 + aK) << 1);
        #pragma unroll
        for (int kt = 0; kt < 16; ++kt) ldsm4(Afrag[kt], aA + ((kt * 16) << 1));
    }

    int bRowBase = (lane & 7) + ((lane >> 4)) * 8;
    int bK = ((lane >> 3) & 1) * 8;
    unsigned bA0 = sptr(sB) + ((bRowBase * 264 + bK) << 1);

    __nv_bfloat16* outp = g_tb + rbase * HDIM;
    for (int ec = 0; ec < 4; ++ec) {
        __syncthreads();
        const __nv_bfloat16* bsrc = g_adjwT + ((long)n * HDIM + ec * 64) * HDIM;
        for (int idx = tid; idx < 64 * 32; idx += 256) {
            int r = idx >> 5, k8 = idx & 31;
            *(float4*)&sB[r * 264 + k8 * 8] = *(const float4*)&bsrc[(long)r * HDIM + k8 * 8];
        }
        __syncthreads();
        #pragma unroll
        for (int ntp = 0; ntp < 4; ++ntp) {
            float c0[4] = {0.f, 0.f, 0.f, 0.f};
            float c1[4] = {0.f, 0.f, 0.f, 0.f};
            unsigned ba = bA0 + ((ntp * 16 * 264) << 1);
            #pragma unroll
            for (int kt = 0; kt < 16; ++kt) {
                unsigned bf[4];
                ldsm4(bf, ba + ((kt * 16) << 1));
                mma16816(c0, Afrag[kt], &bf[0]);
                mma16816(c1, Afrag[kt], &bf[2]);
            }
            int row = w * 16 + gr;
            int col = ec * 64 + ntp * 16 + qp * 2;
            *(__nv_bfloat162*)&outp[(long)row * HDIM + col] = __floats2bfloat162_rn(c0[0], c0[1]);
            *(__nv_bfloat162*)&outp[(long)(row + 8) * HDIM + col] = __floats2bfloat162_rn(c0[2], c0[3]);
            *(__nv_bfloat162*)&outp[(long)row * HDIM + col + 8] = __floats2bfloat162_rn(c1[0], c1[1]);
            *(__nv_bfloat162*)&outp[(long)(row + 8) * HDIM + col + 8] = __floats2bfloat162_rn(c1[2], c1[3]);
        }
    }
}

// ---------------- attention: tensor-core counting + exact fallback ------
#define TH_HI 33.4f
__global__ void __launch_bounds__(256, 2) attn_count_kernel(
    const float* __restrict__ adjw, const float* __restrict__ batt)
{
    extern __shared__ char smraw[];
    __nv_bfloat16* sT  = (__nv_bfloat16*)smraw;    // 128 x 264
    __nv_bfloat16* sB  = sT + 128 * 264;           // 64 x 264 (reused as scratch)
    float* sCol = (float*)(sB + 64 * 264);         // 256
    int*   sCnt = (int*)(sCol + 256);              // 128

    int mb = blockIdx.x, b = blockIdx.y, n = blockIdx.z;
    int tid = threadIdx.x, lane = tid & 31, w = tid >> 5;
    int gr = lane >> 2;
    long nb = (long)(n * 16 + b);
    long base = nb * LSEQ * HDIM;
    int r0 = mb * 128;
    int erow0 = n * BLROWS + b * LSEQ;
    const __nv_bfloat16* hbp = g_hb + base;
    const __nv_bfloat16* tbp = g_tb + base + (long)r0 * HDIM;

    for (int idx = tid; idx < 128 * 32; idx += 256) {
        int r = idx >> 5, k8 = idx & 31;
        *(float4*)&sT[r * 264 + k8 * 8] = *(const float4*)&tbp[(long)r * HDIM + k8 * 8];
    }
    __syncthreads();

    unsigned Afrag[16][4];
    {
        int aRow = w * 16 + (lane & 7) + ((lane >> 3) & 1) * 8;
        int aK = (lane >> 4) * 8;
        unsigned aA = sptr(sT) + ((aRow * 264 + aK) << 1);
        #pragma unroll
        for (int kt = 0; kt < 16; ++kt) ldsm4(Afrag[kt], aA + ((kt * 16) << 1));
    }

    int bRowBase = (lane & 7) + ((lane >> 4)) * 8;
    int bK = ((lane >> 3) & 1) * 8;
    unsigned bA0 = sptr(sB) + ((bRowBase * 264 + bK) << 1);

    int cntA = 0, cntB = 0;
    for (int jc = 0; jc < 16; ++jc) {
        __syncthreads();
        const __nv_bfloat16* bsrc = hbp + (long)jc * 64 * HDIM;
        for (int idx = tid; idx < 64 * 32; idx += 256) {
            int r = idx >> 5, k8 = idx & 31;
            *(float4*)&sB[r * 264 + k8 * 8] = *(const float4*)&bsrc[(long)r * HDIM + k8 * 8];
        }
        __syncthreads();
        #pragma unroll
        for (int ntp = 0; ntp < 4; ++ntp) {
            float c0[4] = {0.f, 0.f, 0.f, 0.f};
            float c1[4] = {0.f, 0.f, 0.f, 0.f};
            unsigned ba = bA0 + ((ntp * 16 * 264) << 1);
            #pragma unroll
            for (int kt = 0; kt < 16; ++kt) {
                unsigned bf[4];
                ldsm4(bf, ba + ((kt * 16) << 1));
                mma16816(c0, Afrag[kt], &bf[0]);
                mma16816(c1, Afrag[kt], &bf[2]);
            }
            cntA += (c0[0] > TH_HI) + (c0[1] > TH_HI) + (c1[0] > TH_HI) + (c1[1] > TH_HI);
            cntB += (c0[2] > TH_HI) + (c0[3] > TH_HI) + (c1[2] > TH_HI) + (c1[3] > TH_HI);
        }
    }
    cntA += __shfl_xor_sync(0xffffffffu, cntA, 1);
    cntA += __shfl_xor_sync(0xffffffffu, cntA, 2);
    cntB += __shfl_xor_sync(0xffffffffu, cntB, 1);
    cntB += __shfl_xor_sync(0xffffffffu, cntB, 2);
    if ((lane & 3) == 0) {
        sCnt[w * 16 + gr] = cntA;
        sCnt[w * 16 + gr + 8] = cntB;
    }
    __syncthreads();

    // column sums of h (fp32) over this CTA's 128 rows
    const float* hfp = g_h + base + (long)r0 * HDIM;
    {
        float cs = 0.f;
        for (int r = 0; r < 128; ++r) cs += hfp[(long)r * HDIM + tid];
        sCol[tid] = cs;
    }
    __syncthreads();

    // exact fallback for uncertain rows (statistically never taken)
    float battn = batt[n];
    for (int r = 0; r < 128; ++r) {
        if (sCnt[r] >= 308) continue;

        float* tI   = (float*)sB;
        float* Srow = tI + 256;
        int*   hist = (int*)(Srow + 1024);
        int*   iv   = hist + 256;

        int gi = r0 + r;
        const float* hrow = g_h + base + (long)gi * HDIM;
        const float* aw = adjw + (long)n * HDIM * HDIM;

        {
            float acc = 0.f;
            for (int d = 0; d < 256; ++d) acc = fmaf(hrow[d], aw[d * 256 + tid], acc);
            tI[tid] = acc;
        }
        __syncthreads();
        for (int j = tid; j < 1024; j += 256) {
            const float* hj = g_h + base + (long)j * HDIM;
            float s = 0.f;
            for (int k = 0; k < 256; ++k) s = fmaf(tI[k], hj[k], s);
            Srow[j] = sigf(s);
        }
        if (tid == 0) iv[0] = 0;
        __syncthreads();
        {
            int c1 = 0;
            for (int j = tid; j < 1024; j += 256) c1 += (Srow[j] >= 1.0f);
            atomicAdd(&iv[0], c1);
        }
        __syncthreads();
        int cnt1 = iv[0];
        if (cnt1 >= 308) { __syncthreads(); continue; }

        if (w == 0) {
            unsigned prefix = 0; int rank = 716;
            for (int p = 3; p >= 0; --p) {
                for (int q2 = lane; q2 < 256; q2 += 32) hist[q2] = 0;
                __syncwarp();
                unsigned himask = (p == 3) ? 0u : (0xFFFFFFFFu << ((p + 1) * 8));
                for (int j = lane; j < 1024; j += 32) {
                    unsigned key = __float_as_uint(Srow[j]);
                    if ((key & himask) == prefix)
                        atomicAdd(&hist[(key >> (p * 8)) & 0xFF], 1);
                }
                __syncwarp();
                int part = 0;
                #pragma unroll
                for (int q2 = 0; q2 < 8; ++q2) part += hist[lane * 8 + q2];
                int scan = part;
                #pragma unroll
                for (int o = 1; o < 32; o <<= 1) {
                    int vv = __shfl_up_sync(0xffffffffu, scan, o);
                    if (lane >= o) scan += vv;
                }
                int excl = scan - part;
                unsigned vote = __ballot_sync(0xffffffffu, (excl <= rank) && (rank < excl + part));
                int srcl = __ffs(vote) - 1;
                int binsel = 0, nrank = 0;
                if (lane == srcl) {
                    int cum = excl;
                    #pragma unroll
                    for (int q2 = 0; q2 < 8; ++q2) {
                        int c = hist[lane * 8 + q2];
                        if (cum + c > rank) { binsel = lane * 8 + q2; nrank = rank - cum; break; }
                        cum += c;
                    }
                }
                binsel = __shfl_sync(0xffffffffu, binsel, srcl);
                rank   = __shfl_sync(0xffffffffu, nrank, srcl);
                prefix |= (unsigned)binsel << (p * 8);
                __syncwarp();
            }
            float v1 = __uint_as_float(prefix);
            int cnt = 0; unsigned mn = 0xFFFFFFFFu;
            for (int j = lane; j < 1024; j += 32) {
                unsigned key = __float_as_uint(Srow[j]);
                if (key <= prefix) cnt++; else mn = min(mn, key);
            }
            #pragma unroll
            for (int o = 16; o; o >>= 1) {
                cnt += __shfl_xor_sync(0xffffffffu, cnt, o);
                mn = min(mn, __shfl_xor_sync(0xffffffffu, mn, o));
            }
            float v2 = (cnt >= 718) ? v1 : __uint_as_float(mn);
            const float frac = (float)(0.7 * 1023.0 - 716.0);
            float delta = v1 + frac * (v2 - v1);

            float es = g_esrc[erow0 + gi];
            float m = -1e30f;
            for (int j = lane; j < 1024; j += 32) {
                if (Srow[j] > delta || j == gi) {
                    float x = es + g_edst[erow0 + j] + battn;
                    float e = x > 0.f ? x : 0.01f * x;
                    m = fmaxf(m, e);
                }
            }
            #pragma unroll
            for (int o = 16; o; o >>= 1) m = fmaxf(m, __shfl_xor_sync(0xffffffffu, m, o));
            float ssum = 0.f;
            for (int j = lane; j < 1024; j += 32) {
                if (Srow[j] > delta || j == gi) {
                    float x = es + g_edst[erow0 + j] + battn;
                    float e = x > 0.f ? x : 0.01f * x;
                    ssum += expf(e - m);
                }
            }
            ssum = wredsum(ssum);
            float inv = 1.f / ssum;
            for (int j = lane; j < 1024; j += 32) {
                bool msk = (Srow[j] > delta) || (j == gi);
                float aj = 0.f;
                if (msk) {
                    float x = es + g_edst[erow0 + j] + battn;
                    float e = x > 0.f ? x : 0.01f * x;
                    aj = expf(e - m) * inv;
                }
                Srow[j] = aj;
            }
        }
        __syncthreads();
        {
            float acc = 0.f;
            for (int j = 0; j < 1024; ++j)
                acc = fmaf(Srow[j], g_h[base + (long)j * HDIM + tid], acc);
            sCol[tid] += acc - hrow[tid];
        }
        __syncthreads();
    }

    g_partial[(nb * 8 + mb) * 256 + tid] = sCol[tid];
}

// ---------------- final: means -> 3 GEMMs -> LN -> d_out ----------------
__global__ void __launch_bounds__(256) final_kernel(
    const float* __restrict__ W0, const float* __restrict__ b0,
    const float* __restrict__ W1, const float* __restrict__ b1,
    const float* __restrict__ W2, const float* __restrict__ b2,
    const float* __restrict__ g0, const float* __restrict__ be0,
    const float* __restrict__ g1, const float* __restrict__ be1,
    const float* __restrict__ g2, const float* __restrict__ be2,
    float* __restrict__ out)
{
    __shared__ float vin[1024];
    __shared__ float red[40];
    int which = blockIdx.x, b = blockIdx.y, tid = threadIdx.x;
    int K = (which == 2) ? 1024 : 512;
    int hb2 = (which == 1) ? 2 : 0;

    for (int e = tid; e < K; e += 256) {
        int n = hb2 + (e >> 8), col = e & 255;
        const float* p = g_partial + ((long)(n * 16 + b) * 8) * 256 + col;
        float s = 0.f;
        #pragma unroll
        for (int ibk = 0; ibk < 8; ++ibk) s += p[ibk * 256];
        vin[e] = s * (1.f / 1024.f);
    }
    __syncthreads();

    const float* W  = (which == 0) ? W0 : ((which == 1) ? W1 : W2);
    const float* bi = (which == 0) ? b0 : ((which == 1) ? b1 : b2);
    const float* g  = (which == 0) ? g0 : ((which == 1) ? g1 : g2);
    const float* be = (which == 0) ? be0 : ((which == 1) ? be1 : be2);

    float acc3[3];
    #pragma unroll
    for (int oi = 0; oi < 3; ++oi) {
        int o = tid + oi * 256;
        float a = bi[o];
        for (int k = 0; k < K; ++k) a = fmaf(vin[k], W[(long)k * OUTD + o], a);
        acc3[oi] = a;
    }

    float ls = acc3[0] + acc3[1] + acc3[2];
    ls = wredsum(ls);
    if ((tid & 31) == 0) red[tid >> 5] = ls;
    __syncthreads();
    if (tid == 0) {
        float s = 0.f;
        for (int q = 0; q < 8; ++q) s += red[q];
        red[32] = s * (1.f / 768.f);
    }
    __syncthreads();
    float mu = red[32];
    __syncthreads();
    float vv = 0.f;
    #pragma unroll
    for (int oi = 0; oi < 3; ++oi) { float d = acc3[oi] - mu; vv += d * d; }
    vv = wredsum(vv);
    if ((tid & 31) == 0) red[tid >> 5] = vv;
    __syncthreads();
    if (tid == 0) {
        float s = 0.f;
        for (int q = 0; q < 8; ++q) s += red[q];
        red[33] = s * (1.f / 768.f);
    }
    __syncthreads();
    float rstd = rsqrtf(red[33] + 1e-5f);
    #pragma unroll
    for (int oi = 0; oi < 3; ++oi) {
        int o = tid + oi * 256;
        out[(long)which * BB * OUTD + (long)b * OUTD + o] = (acc3[oi] - mu) * rstd * g[o] + be[o];
    }
}

// ---------------- launch ----------------
extern "C" void kernel_launch(void* const* d_in, const int* in_sizes, int n_in,
                              void* d_out, int out_size)
{
    const float* x    = (const float*)d_in[0];
    const float* Wfc  = (const float*)d_in[1];
    const float* bfc  = (const float*)d_in[2];
    const float* lng  = (const float*)d_in[3];
    const float* lnb  = (const float*)d_in[4];
    const float* adjw = (const float*)d_in[5];
    const float* Watt = (const float*)d_in[6];
    const float* batt = (const float*)d_in[7];
    const float* Wl = (const float*)d_in[8];  const float* bl = (const float*)d_in[9];
    const float* Ws = (const float*)d_in[10]; const float* bs = (const float*)d_in[11];
    const float* Wc = (const float*)d_in[12]; const float* bc = (const float*)d_in[13];
    const float* gl = (const float*)d_in[14]; const float* bel = (const float*)d_in[15];
    const float* gs = (const float*)d_in[16]; const float* bes = (const float*)d_in[17];
    const float* gc = (const float*)d_in[18]; const float* bec = (const float*)d_in[19];
    float* out = (float*)d_out;

    // 0) prep: splits + transposes
    split_x_kernel<<<(BLROWS * DDIM) / 1024, 256>>>(x);
    split_W_kernel<<<dim3(HDIM, NHEAD), 256>>>(Wfc);
    adjwT_kernel<<<dim3(HDIM, NHEAD), 256>>>(adjw);

    // 1) h_pre = x @ Wfc + bfc (bf16-split tensor)
    fc_gemm_kernel<<<dim3(8, BLROWS / 128), 256>>>(bfc);

    // 2) LN in place + e_src/e_dst + bf16 h
    ln_att_kernel<<<(NHEAD * BLROWS) / 8, 256>>>(lng, lnb, Watt);

    // 3) tb = hb @ adjw (bf16 tensor)
    const int smemTB = (128 * 264 + 64 * 264) * 2;
    cudaFuncSetAttribute(tb_gemm_kernel, cudaFuncAttributeMaxDynamicSharedMemorySize, smemTB);
    tb_gemm_kernel<<<dim3(BLROWS / 128, NHEAD), 256, smemTB>>>();

    // 4) attention counting + fallback + partial means
    const int smemAT = (128 * 264 + 64 * 264) * 2 + 256 * 4 + 128 * 4 + 64;
    cudaFuncSetAttribute(attn_count_kernel, cudaFuncAttributeMaxDynamicSharedMemorySize, smemAT);
    attn_count_kernel<<<dim3(8, BB, NHEAD), 256, smemAT>>>(adjw, batt);

    // 5) finals
    final_kernel<<<dim3(3, BB), 256>>>(Wl, bl, Ws, bs, Wc, bc, gl, bel, gs, bes, gc, bec, out);
}